// round 10
// baseline (speedup 1.0000x reference)
#include <cuda_runtime.h>
#include <math.h>
#include <stdint.h>

// Problem constants
#define BATCH 2
#define TDIM 2048
#define CDIM 1024
#define HN 16
#define HD 64
#define BT (BATCH * TDIM)        // 4096 rows
#define BH (BATCH * HN)          // 32 batch-heads
#define QKVC (3 * CDIM)          // 3072
#define FFC (4 * CDIM)           // 4096

#define NEG_BIG (-1e30f)

// -------- scratch (static device globals; no allocation) ----------
__device__ float g_h[BT * CDIM];
__device__ float g_qkv[BT * QKVC];
__device__ float g_y[BT * CDIM];
__device__ float g_x1[BT * CDIM];
__device__ float g_m[BT * FFC];
__device__ float g_wr[12582912];   // RN-rounded weights: attn|attnproj|fc|proj
__device__ float g_ent;

#define WR_ATTN  0
#define WR_APROJ 3145728
#define WR_FC    4194304
#define WR_PROJ  8388608

// ------------------------------------------------------------------
__global__ void zero_ent_kernel() { g_ent = 0.0f; }

__global__ void finalize_kernel(float* out, int out_size) {
    if (out_size > BT * CDIM)
        out[BT * CDIM] = g_ent * (1.0f / (float)(BH * TDIM));
}

// -------- helpers -------------------------------------------------
__device__ __forceinline__ float rtf(float x) {   // round-to-nearest tf32
    uint32_t u; asm("cvt.rna.tf32.f32 %0, %1;" : "=r"(u) : "f"(x));
    return __uint_as_float(u);
}

__device__ __forceinline__ void cp16(void* s, const void* g) {
    unsigned sa = (unsigned)__cvta_generic_to_shared(s);
    asm volatile("cp.async.cg.shared.global [%0], [%1], 16;" :: "r"(sa), "l"(g));
}
#define CP_COMMIT() asm volatile("cp.async.commit_group;")
#define CP_WAIT0()  asm volatile("cp.async.wait_group 0;")

__device__ __forceinline__ void mma_tf32(float* c, const unsigned* a, const unsigned* b) {
    asm("mma.sync.aligned.m16n8k8.row.col.f32.tf32.tf32.f32 "
        "{%0,%1,%2,%3}, {%4,%5,%6,%7}, {%8,%9}, {%0,%1,%2,%3};"
        : "+f"(c[0]), "+f"(c[1]), "+f"(c[2]), "+f"(c[3])
        : "r"(a[0]), "r"(a[1]), "r"(a[2]), "r"(a[3]), "r"(b[0]), "r"(b[1]));
}

// -------- weight rounding (4 floats/thread — measured fastest) ----
__global__ void round4_kernel(const float* __restrict__ in,
                              float* __restrict__ out, int n) {
    int i = (blockIdx.x * blockDim.x + threadIdx.x) * 4;
    if (i < n) {
        float4 v = *(const float4*)&in[i];
        v.x = rtf(v.x); v.y = rtf(v.y); v.z = rtf(v.z); v.w = rtf(v.w);
        *(float4*)&out[i] = v;
    }
}

// -------- LayerNorm: float4 path, two-level shuffle reduction -----
__global__ void ln_kernel(const float* __restrict__ x,
                          const float* __restrict__ w,
                          const float* __restrict__ b,
                          float* __restrict__ out) {
    int row = blockIdx.x;
    int tid = threadIdx.x;
    int lane = tid & 31, warp = tid >> 5;
    const float* xr = x + (size_t)row * CDIM;
    __shared__ float rs[8], rq[8];

    float4 v = *(const float4*)&xr[tid * 4];
    float lsum = v.x + v.y + v.z + v.w;
    float lsq  = v.x * v.x + v.y * v.y + v.z * v.z + v.w * v.w;
#pragma unroll
    for (int o = 16; o > 0; o >>= 1) {
        lsum += __shfl_xor_sync(0xFFFFFFFFu, lsum, o);
        lsq  += __shfl_xor_sync(0xFFFFFFFFu, lsq, o);
    }
    if (lane == 0) { rs[warp] = lsum; rq[warp] = lsq; }
    __syncthreads();
    float tsum, tsq;
    {
        float a = rs[lane & 7], c = rq[lane & 7];
#pragma unroll
        for (int o = 4; o > 0; o >>= 1) {
            a += __shfl_xor_sync(0xFFFFFFFFu, a, o);
            c += __shfl_xor_sync(0xFFFFFFFFu, c, o);
        }
        tsum = a; tsq = c;
    }
    float mean = tsum * (1.0f / CDIM);
    float var = tsq * (1.0f / CDIM) - mean * mean;
    float rstd = rsqrtf(var + 1e-5f);

    float4 wv = *(const float4*)&w[tid * 4];
    float4 bv = *(const float4*)&b[tid * 4];
    float4 o4;
    o4.x = rtf((v.x - mean) * rstd * wv.x + bv.x);
    o4.y = rtf((v.y - mean) * rstd * wv.y + bv.y);
    o4.z = rtf((v.z - mean) * rstd * wv.z + bv.z);
    o4.w = rtf((v.w - mean) * rstd * wv.w + bv.w);
    *(float4*)&out[(size_t)row * CDIM + tid * 4] = o4;
}

__device__ __forceinline__ float gelu_tanh(float x) {
    const float k0 = 0.7978845608028654f;
    const float k1 = 0.044715f;
    float u = k0 * (x + k1 * x * x * x);
    float t = __expf(2.0f * u);
    float th = (t - 1.0f) / (t + 1.0f);
    return 0.5f * x * (1.0f + th);
}

// -------- tf32 tensor-core GEMM: C = A[M,K]*W[N,K]^T + bias --------
// 128x128x32 CTA tile, 128 threads, warp grid 2(m)x2(n), warp tile 64x64.
// 3-stage cp.async pipeline, ONE __syncthreads per k-tile, 2 CTAs/SM.
// Rationale: larger warp N-tile amortizes fragment LDS -> 2.1 issue
// slots per MMA (was 2.6).
#define GST 36
#define GBUF (128 * GST)

__global__ __launch_bounds__(128, 2)
void gemm_tc(const float* __restrict__ A, const float* __restrict__ W,
             const float* __restrict__ bias, const float* __restrict__ resid,
             float* __restrict__ C, int M, int N, int K, int act, int rnd) {
    extern __shared__ float sm[];
    float* As = sm;                  // [3][128][36]
    float* Ws = sm + 3 * GBUF;       // [3][128][36]

    int tid = threadIdx.x;
    int warp = tid >> 5, lane = tid & 31;
    int wm = warp >> 1, wn = warp & 1;
    int g = lane >> 2, tig = lane & 3;
    int rowBase = blockIdx.y * 128, colBase = blockIdx.x * 128;
    const float* Ap = A + (size_t)rowBase * K;
    const float* Wp = W + (size_t)colBase * K;

    float acc[4][8][4];
#pragma unroll
    for (int i = 0; i < 4; i++)
#pragma unroll
        for (int j = 0; j < 8; j++)
#pragma unroll
            for (int p = 0; p < 4; p++) acc[i][j][p] = 0.f;

    int lr = tid >> 3;          // 0..15
    int lc = (tid & 7) * 4;     // 0,4,...,28

    // prologue: stage tiles 0 and 1
#pragma unroll
    for (int pt = 0; pt < 2; pt++) {
        int kt = pt << 5;
#pragma unroll
        for (int it = 0; it < 8; it++) {
            int r = lr + it * 16;
            cp16(&As[pt * GBUF + r * GST + lc], Ap + (size_t)r * K + kt + lc);
            cp16(&Ws[pt * GBUF + r * GST + lc], Wp + (size_t)r * K + kt + lc);
        }
        CP_COMMIT();
    }

    int nt = K >> 5;
    int buf = 0;
    for (int t = 0; t < nt; t++) {
        if (t == nt - 1) asm volatile("cp.async.wait_group 0;" ::: "memory");
        else             asm volatile("cp.async.wait_group 1;" ::: "memory");
        __syncthreads();
        if (t + 2 < nt) {
            int kt = (t + 2) << 5;
            int nb = buf >= 1 ? buf - 1 : buf + 2;   // (t+2)%3
#pragma unroll
            for (int it = 0; it < 8; it++) {
                int r = lr + it * 16;
                cp16(&As[nb * GBUF + r * GST + lc], Ap + (size_t)r * K + kt + lc);
                cp16(&Ws[nb * GBUF + r * GST + lc], Wp + (size_t)r * K + kt + lc);
            }
            CP_COMMIT();
        }
        const float* Ab = As + buf * GBUF;
        const float* Wb = Ws + buf * GBUF;
#pragma unroll
        for (int ks = 0; ks < 4; ks++) {
            unsigned af[4][4], bf[8][2];
#pragma unroll
            for (int mi = 0; mi < 4; mi++) {
                int r0 = wm * 64 + mi * 16 + g;
                af[mi][0] = __float_as_uint(Ab[r0 * GST + ks * 8 + tig]);
                af[mi][1] = __float_as_uint(Ab[(r0 + 8) * GST + ks * 8 + tig]);
                af[mi][2] = __float_as_uint(Ab[r0 * GST + ks * 8 + tig + 4]);
                af[mi][3] = __float_as_uint(Ab[(r0 + 8) * GST + ks * 8 + tig + 4]);
            }
#pragma unroll
            for (int nj = 0; nj < 8; nj++) {
                int c0 = wn * 64 + nj * 8 + g;
                bf[nj][0] = __float_as_uint(Wb[c0 * GST + ks * 8 + tig]);
                bf[nj][1] = __float_as_uint(Wb[c0 * GST + ks * 8 + tig + 4]);
            }
#pragma unroll
            for (int mi = 0; mi < 4; mi++)
#pragma unroll
                for (int nj = 0; nj < 8; nj++)
                    mma_tf32(acc[mi][nj], af[mi], bf[nj]);
        }
        buf = buf < 2 ? buf + 1 : 0;
    }

    // epilogue
#pragma unroll
    for (int mi = 0; mi < 4; mi++) {
#pragma unroll
        for (int h2 = 0; h2 < 2; h2++) {
            int r = rowBase + wm * 64 + mi * 16 + g + h2 * 8;
            float* crow = C + (size_t)r * N;
            const float* rrow = resid ? resid + (size_t)r * N : nullptr;
#pragma unroll
            for (int nj = 0; nj < 8; nj++) {
                int c = colBase + wn * 64 + nj * 8 + 2 * tig;
                float v0 = acc[mi][nj][h2 * 2]     + bias[c];
                float v1 = acc[mi][nj][h2 * 2 + 1] + bias[c + 1];
                if (act == 1) { v0 = gelu_tanh(v0); v1 = gelu_tanh(v1); }
                if (rrow) { v0 += rrow[c]; v1 += rrow[c + 1]; }
                if (rnd) { v0 = rtf(v0); v1 = rtf(v1); }
                *(float2*)&crow[c] = make_float2(v0, v1);
            }
        }
    }
}

// -------- Flash attention: 128q x 64k tiles, per-warp pipeline -----
// 2 CTAs/SM (smem ~107KB x2 <= 228KB).
#define QS 68
#define VSS 72
#define KB1 (64 * QS)
#define VB1 (64 * VSS)

__global__ __launch_bounds__(256, 2)
void flash_attn_tc(const float* __restrict__ qkv, float* __restrict__ y) {
    extern __shared__ float smf[];
    float* Ks = smf;                  // [2][64][68]
    float* Vs = Ks + 2 * KB1;         // [2][64][72]
    float* Ps = Vs + 2 * VB1;         // [128][68]  Q staging, then P probs
    float* hrow = Ps + 128 * QS;      // [128]

    int tid = threadIdx.x;
    int warp = tid >> 5, lane = tid & 31;
    int g = lane >> 2, tig = lane & 3;
    int qt = (TDIM / 128 - 1) - blockIdx.x;   // long tiles first
    int bh = blockIdx.y;
    int b = bh >> 4, h = bh & 15;
    int qb = qt * 128;
    const float* base = qkv + (size_t)b * TDIM * QKVC + h * HD;

    // prefetch Q (128x64 -> Ps) + K0 + V0
#pragma unroll
    for (int i = 0; i < 8; i++) {
        int ch = tid + i * 256; int r = ch >> 4; int c = (ch & 15) * 4;
        cp16(&Ps[r * QS + c], &base[(size_t)(qb + r) * QKVC + c]);
    }
#pragma unroll
    for (int i = 0; i < 4; i++) {
        int ch = tid + i * 256; int r = ch >> 4; int c = (ch & 15) * 4;
        cp16(&Ks[r * QS + c], &base[(size_t)r * QKVC + CDIM + c]);
        cp16(&Vs[r * VSS + c], &base[(size_t)r * QKVC + 2 * CDIM + c]);
    }
    CP_COMMIT();
    CP_WAIT0();
    __syncthreads();

    // hoist Q fragments (warp's 16 rows x 64 d)
    int r0l = warp * 16 + g;
    unsigned qf[8][4];
#pragma unroll
    for (int ks = 0; ks < 8; ks++) {
        qf[ks][0] = __float_as_uint(Ps[r0l * QS + ks * 8 + tig]);
        qf[ks][1] = __float_as_uint(Ps[(r0l + 8) * QS + ks * 8 + tig]);
        qf[ks][2] = __float_as_uint(Ps[r0l * QS + ks * 8 + tig + 4]);
        qf[ks][3] = __float_as_uint(Ps[(r0l + 8) * QS + ks * 8 + tig + 4]);
    }

    float m0 = NEG_BIG, m1 = NEG_BIG, l0 = 0.f, l1 = 0.f, w0 = 0.f, w1 = 0.f;
    float oacc[8][4];
#pragma unroll
    for (int nj = 0; nj < 8; nj++)
#pragma unroll
        for (int p = 0; p < 4; p++) oacc[nj][p] = 0.f;

    int row0 = qb + warp * 16 + g, row1 = row0 + 8;
    int ni = 2 * qt + 2;

    for (int i = 0; i < ni; i++) {
        CP_WAIT0();
        __syncthreads();
        if (i + 1 < ni) {
            int nb = (i + 1) & 1, kb2 = (i + 1) * 64;
#pragma unroll
            for (int it = 0; it < 4; it++) {
                int ch = tid + it * 256; int r = ch >> 4; int c = (ch & 15) * 4;
                cp16(&Ks[nb * KB1 + r * QS + c],
                     &base[(size_t)(kb2 + r) * QKVC + CDIM + c]);
                cp16(&Vs[nb * VB1 + r * VSS + c],
                     &base[(size_t)(kb2 + r) * QKVC + 2 * CDIM + c]);
            }
            CP_COMMIT();
        }
        int kb = i * 64;
        if (qb + warp * 16 + 15 >= kb) {   // warp has unmasked rows here
            const float* Kb = Ks + (i & 1) * KB1;
            const float* Vb = Vs + (i & 1) * VB1;

            // ---- S = Q K^T (registers) ----
            float sacc[8][4];
#pragma unroll
            for (int nj = 0; nj < 8; nj++)
#pragma unroll
                for (int p = 0; p < 4; p++) sacc[nj][p] = 0.f;
#pragma unroll
            for (int ks = 0; ks < 8; ks++) {
#pragma unroll
                for (int nj = 0; nj < 8; nj++) {
                    int c0 = nj * 8 + g;
                    unsigned bf[2];
                    bf[0] = __float_as_uint(Kb[c0 * QS + ks * 8 + tig]);
                    bf[1] = __float_as_uint(Kb[c0 * QS + ks * 8 + tig + 4]);
                    mma_tf32(sacc[nj], qf[ks], bf);
                }
            }

            // ---- scale + mask + row max ----
            float mx0 = NEG_BIG, mx1 = NEG_BIG;
#pragma unroll
            for (int nj = 0; nj < 8; nj++) {
                int cg = kb + nj * 8 + 2 * tig;
                float s0 = sacc[nj][0] * 0.125f;
                float s1 = sacc[nj][1] * 0.125f;
                float s2 = sacc[nj][2] * 0.125f;
                float s3 = sacc[nj][3] * 0.125f;
                if (cg > row0) s0 = NEG_BIG;
                if (cg + 1 > row0) s1 = NEG_BIG;
                if (cg > row1) s2 = NEG_BIG;
                if (cg + 1 > row1) s3 = NEG_BIG;
                sacc[nj][0] = s0; sacc[nj][1] = s1;
                sacc[nj][2] = s2; sacc[nj][3] = s3;
                mx0 = fmaxf(mx0, fmaxf(s0, s1));
                mx1 = fmaxf(mx1, fmaxf(s2, s3));
            }
            mx0 = fmaxf(mx0, __shfl_xor_sync(0xFFFFFFFFu, mx0, 1));
            mx0 = fmaxf(mx0, __shfl_xor_sync(0xFFFFFFFFu, mx0, 2));
            mx1 = fmaxf(mx1, __shfl_xor_sync(0xFFFFFFFFu, mx1, 1));
            mx1 = fmaxf(mx1, __shfl_xor_sync(0xFFFFFFFFu, mx1, 2));
            float mn0 = fmaxf(m0, mx0), mn1 = fmaxf(m1, mx1);

            // ---- exp + sums + write P ----
            float se0 = 0.f, se1 = 0.f, sw0 = 0.f, sw1 = 0.f;
#pragma unroll
            for (int nj = 0; nj < 8; nj++) {
                float s0 = sacc[nj][0], s1 = sacc[nj][1];
                float s2 = sacc[nj][2], s3 = sacc[nj][3];
                float e0 = __expf(s0 - mn0), e1 = __expf(s1 - mn0);
                float e2 = __expf(s2 - mn1), e3 = __expf(s3 - mn1);
                se0 += e0 + e1; sw0 += e0 * s0 + e1 * s1;
                se1 += e2 + e3; sw1 += e2 * s2 + e3 * s3;
                int c0 = nj * 8 + 2 * tig;
                *(float2*)&Ps[(warp * 16 + g) * QS + c0] =
                    make_float2(rtf(e0), rtf(e1));
                *(float2*)&Ps[(warp * 16 + g + 8) * QS + c0] =
                    make_float2(rtf(e2), rtf(e3));
            }
            se0 += __shfl_xor_sync(0xFFFFFFFFu, se0, 1);
            se0 += __shfl_xor_sync(0xFFFFFFFFu, se0, 2);
            sw0 += __shfl_xor_sync(0xFFFFFFFFu, sw0, 1);
            sw0 += __shfl_xor_sync(0xFFFFFFFFu, sw0, 2);
            se1 += __shfl_xor_sync(0xFFFFFFFFu, se1, 1);
            se1 += __shfl_xor_sync(0xFFFFFFFFu, se1, 2);
            sw1 += __shfl_xor_sync(0xFFFFFFFFu, sw1, 1);
            sw1 += __shfl_xor_sync(0xFFFFFFFFu, sw1, 2);

            float c0f = __expf(m0 - mn0), c1f = __expf(m1 - mn1);
            l0 = l0 * c0f + se0; w0 = w0 * c0f + sw0; m0 = mn0;
            l1 = l1 * c1f + se1; w1 = w1 * c1f + sw1; m1 = mn1;
#pragma unroll
            for (int nj = 0; nj < 8; nj++) {
                oacc[nj][0] *= c0f; oacc[nj][1] *= c0f;
                oacc[nj][2] *= c1f; oacc[nj][3] *= c1f;
            }
            __syncwarp();

            // ---- O += P V ----
#pragma unroll
            for (int ks = 0; ks < 8; ks++) {
                unsigned af[4];
                af[0] = __float_as_uint(Ps[r0l * QS + ks * 8 + tig]);
                af[1] = __float_as_uint(Ps[(r0l + 8) * QS + ks * 8 + tig]);
                af[2] = __float_as_uint(Ps[r0l * QS + ks * 8 + tig + 4]);
                af[3] = __float_as_uint(Ps[(r0l + 8) * QS + ks * 8 + tig + 4]);
#pragma unroll
                for (int nj = 0; nj < 8; nj++) {
                    int d0 = nj * 8 + g;
                    unsigned bf[2];
                    bf[0] = __float_as_uint(Vb[(ks * 8 + tig) * VSS + d0]);
                    bf[1] = __float_as_uint(Vb[(ks * 8 + tig + 4) * VSS + d0]);
                    mma_tf32(oacc[nj], af, bf);
                }
            }
            __syncwarp();
        }
    }

    // write O (divide by l, RN-round: operand of attnproj GEMM)
    {
        float li0 = 1.0f / l0, li1 = 1.0f / l1;
#pragma unroll
        for (int nj = 0; nj < 8; nj++) {
            int c = h * HD + nj * 8 + 2 * tig;
            *(float2*)&y[(size_t)(b * TDIM + row0) * CDIM + c] =
                make_float2(rtf(oacc[nj][0] * li0), rtf(oacc[nj][1] * li0));
            *(float2*)&y[(size_t)(b * TDIM + row1) * CDIM + c] =
                make_float2(rtf(oacc[nj][2] * li1), rtf(oacc[nj][3] * li1));
        }
    }

    // entropy: H_row = m + log(S) - W/S
    if (tig == 0) {
        hrow[warp * 16 + g]     = m0 + logf(l0) - w0 / l0;
        hrow[warp * 16 + g + 8] = m1 + logf(l1) - w1 / l1;
    }
    __syncthreads();
    if (tid == 0) {
        float tot = 0.f;
        for (int i = 0; i < 128; i++) tot += hrow[i];
        atomicAdd(&g_ent, tot);
    }
}

// ------------------------------------------------------------------
extern "C" void kernel_launch(void* const* d_in, const int* in_sizes, int n_in,
                              void* d_out, int out_size) {
    const float* x          = (const float*)d_in[0];
    const float* ln1_w      = (const float*)d_in[1];
    const float* ln1_b      = (const float*)d_in[2];
    const float* attn_w     = (const float*)d_in[3];
    const float* attn_b     = (const float*)d_in[4];
    const float* attnproj_w = (const float*)d_in[5];
    const float* attnproj_b = (const float*)d_in[6];
    const float* ln2_w      = (const float*)d_in[7];
    const float* ln2_b      = (const float*)d_in[8];
    const float* fc_w       = (const float*)d_in[9];
    const float* fc_b       = (const float*)d_in[10];
    const float* proj_w     = (const float*)d_in[11];
    const float* proj_b     = (const float*)d_in[12];
    float* out = (float*)d_out;

    float *p_h, *p_qkv, *p_y, *p_x1, *p_m, *p_wr;
    cudaGetSymbolAddress((void**)&p_h,   g_h);
    cudaGetSymbolAddress((void**)&p_qkv, g_qkv);
    cudaGetSymbolAddress((void**)&p_y,   g_y);
    cudaGetSymbolAddress((void**)&p_x1,  g_x1);
    cudaGetSymbolAddress((void**)&p_m,   g_m);
    cudaGetSymbolAddress((void**)&p_wr,  g_wr);

    static int gemm_smem = 6 * GBUF * 4;                            // 110592 B
    static int attn_smem = (2 * KB1 + 2 * VB1 + 128 * QS + 128) * 4; // ~107 KB
    cudaFuncSetAttribute(gemm_tc,
                         cudaFuncAttributeMaxDynamicSharedMemorySize, gemm_smem);
    cudaFuncSetAttribute(flash_attn_tc,
                         cudaFuncAttributeMaxDynamicSharedMemorySize, attn_smem);

    zero_ent_kernel<<<1, 1>>>();

    // RN-round weights to tf32 once per launch
    round4_kernel<<<3145728 / 1024, 256>>>(attn_w,     p_wr + WR_ATTN,  3145728);
    round4_kernel<<<1048576 / 1024, 256>>>(attnproj_w, p_wr + WR_APROJ, 1048576);
    round4_kernel<<<4194304 / 1024, 256>>>(fc_w,       p_wr + WR_FC,    4194304);
    round4_kernel<<<4194304 / 1024, 256>>>(proj_w,     p_wr + WR_PROJ,  4194304);

    // h = LN1(x)  (RN tf32)
    ln_kernel<<<BT, 256>>>(x, ln1_w, ln1_b, p_h);

    // qkv = h @ attn_w^T + attn_b
    gemm_tc<<<dim3(QKVC / 128, BT / 128), 128, gemm_smem>>>(
        p_h, p_wr + WR_ATTN, attn_b, nullptr, p_qkv, BT, QKVC, CDIM, 0, 1);

    // attention (+entropy)
    flash_attn_tc<<<dim3(TDIM / 128, BH), 256, attn_smem>>>(p_qkv, p_y);

    // x1 = x + y @ attnproj_w^T + attnproj_b
    gemm_tc<<<dim3(CDIM / 128, BT / 128), 128, gemm_smem>>>(
        p_y, p_wr + WR_APROJ, attnproj_b, x, p_x1, BT, CDIM, CDIM, 0, 0);

    // h = LN2(x1)  (RN tf32)
    ln_kernel<<<BT, 256>>>(p_x1, ln2_w, ln2_b, p_h);

    // m = gelu(h @ fc_w^T + fc_b)
    gemm_tc<<<dim3(FFC / 128, BT / 128), 128, gemm_smem>>>(
        p_h, p_wr + WR_FC, fc_b, nullptr, p_m, BT, FFC, CDIM, 1, 1);

    // out = x1 + m @ proj_w^T + proj_b
    gemm_tc<<<dim3(CDIM / 128, BT / 128), 128, gemm_smem>>>(
        p_m, p_wr + WR_PROJ, proj_b, p_x1, out, BT, CDIM, FFC, 0, 0);

    // entropy scalar
    finalize_kernel<<<1, 1>>>(out, out_size);
}

// round 11
// speedup vs baseline: 1.4822x; 1.4822x over previous
#include <cuda_runtime.h>
#include <cuda_fp16.h>
#include <math.h>
#include <stdint.h>

// Problem constants
#define BATCH 2
#define TDIM 2048
#define CDIM 1024
#define HN 16
#define HD 64
#define BT (BATCH * TDIM)        // 4096 rows
#define BH (BATCH * HN)          // 32 batch-heads
#define QKVC (3 * CDIM)          // 3072
#define FFC (4 * CDIM)           // 4096

#define NEG_BIG (-1e30f)

// -------- scratch (static device globals; no allocation) ----------
__device__ __half g_h[BT * CDIM];      // LN output (GEMM A operand)
__device__ float  g_qkv[BT * QKVC];    // qkv (fp32, tf32-rounded: attention operand)
__device__ __half g_y[BT * CDIM];      // attention out (attnproj A operand)
__device__ float  g_x1[BT * CDIM];     // x + attn (fp32 residual)
__device__ __half g_m[BT * FFC];       // gelu(fc) (proj A operand)
__device__ __half g_wh[12582912];      // fp16 weights: attn|attnproj|fc|proj
__device__ float  g_ent;

#define WR_ATTN  0
#define WR_APROJ 3145728
#define WR_FC    4194304
#define WR_PROJ  8388608

// ------------------------------------------------------------------
__global__ void zero_ent_kernel() { g_ent = 0.0f; }

__global__ void finalize_kernel(float* out, int out_size) {
    if (out_size > BT * CDIM)
        out[BT * CDIM] = g_ent * (1.0f / (float)(BH * TDIM));
}

// -------- helpers -------------------------------------------------
__device__ __forceinline__ float rtf(float x) {   // round-to-nearest tf32
    uint32_t u; asm("cvt.rna.tf32.f32 %0, %1;" : "=r"(u) : "f"(x));
    return __uint_as_float(u);
}

__device__ __forceinline__ void cp16(void* s, const void* g) {
    unsigned sa = (unsigned)__cvta_generic_to_shared(s);
    asm volatile("cp.async.cg.shared.global [%0], [%1], 16;" :: "r"(sa), "l"(g));
}
#define CP_COMMIT() asm volatile("cp.async.commit_group;")
#define CP_WAIT0()  asm volatile("cp.async.wait_group 0;")

__device__ __forceinline__ void mma_tf32(float* c, const unsigned* a, const unsigned* b) {
    asm("mma.sync.aligned.m16n8k8.row.col.f32.tf32.tf32.f32 "
        "{%0,%1,%2,%3}, {%4,%5,%6,%7}, {%8,%9}, {%0,%1,%2,%3};"
        : "+f"(c[0]), "+f"(c[1]), "+f"(c[2]), "+f"(c[3])
        : "r"(a[0]), "r"(a[1]), "r"(a[2]), "r"(a[3]), "r"(b[0]), "r"(b[1]));
}

__device__ __forceinline__ void mma_f16(float* c, const unsigned* a, const unsigned* b) {
    asm("mma.sync.aligned.m16n8k16.row.col.f32.f16.f16.f32 "
        "{%0,%1,%2,%3}, {%4,%5,%6,%7}, {%8,%9}, {%0,%1,%2,%3};"
        : "+f"(c[0]), "+f"(c[1]), "+f"(c[2]), "+f"(c[3])
        : "r"(a[0]), "r"(a[1]), "r"(a[2]), "r"(a[3]), "r"(b[0]), "r"(b[1]));
}

// -------- weight conversion fp32 -> fp16 (RN) ---------------------
__global__ void tohalf_kernel(const float* __restrict__ in,
                              __half* __restrict__ out, int n) {
    int i = (blockIdx.x * blockDim.x + threadIdx.x) * 4;
    if (i < n) {
        float4 v = *(const float4*)&in[i];
        __half2 a = __floats2half2_rn(v.x, v.y);
        __half2 b = __floats2half2_rn(v.z, v.w);
        *(__half2*)&out[i]     = a;
        *(__half2*)&out[i + 2] = b;
    }
}

// -------- LayerNorm: fp32 in, fp16 out ----------------------------
__global__ void ln_kernel(const float* __restrict__ x,
                          const float* __restrict__ w,
                          const float* __restrict__ b,
                          __half* __restrict__ out) {
    int row = blockIdx.x;
    int tid = threadIdx.x;
    int lane = tid & 31, warp = tid >> 5;
    const float* xr = x + (size_t)row * CDIM;
    __shared__ float rs[8], rq[8];

    float4 v = *(const float4*)&xr[tid * 4];
    float lsum = v.x + v.y + v.z + v.w;
    float lsq  = v.x * v.x + v.y * v.y + v.z * v.z + v.w * v.w;
#pragma unroll
    for (int o = 16; o > 0; o >>= 1) {
        lsum += __shfl_xor_sync(0xFFFFFFFFu, lsum, o);
        lsq  += __shfl_xor_sync(0xFFFFFFFFu, lsq, o);
    }
    if (lane == 0) { rs[warp] = lsum; rq[warp] = lsq; }
    __syncthreads();
    float tsum, tsq;
    {
        float a = rs[lane & 7], c = rq[lane & 7];
#pragma unroll
        for (int o = 4; o > 0; o >>= 1) {
            a += __shfl_xor_sync(0xFFFFFFFFu, a, o);
            c += __shfl_xor_sync(0xFFFFFFFFu, c, o);
        }
        tsum = a; tsq = c;
    }
    float mean = tsum * (1.0f / CDIM);
    float var = tsq * (1.0f / CDIM) - mean * mean;
    float rstd = rsqrtf(var + 1e-5f);

    float4 wv = *(const float4*)&w[tid * 4];
    float4 bv = *(const float4*)&b[tid * 4];
    __half2* orow = (__half2*)(out + (size_t)row * CDIM);
    orow[tid * 2] = __floats2half2_rn((v.x - mean) * rstd * wv.x + bv.x,
                                      (v.y - mean) * rstd * wv.y + bv.y);
    orow[tid * 2 + 1] = __floats2half2_rn((v.z - mean) * rstd * wv.z + bv.z,
                                          (v.w - mean) * rstd * wv.w + bv.w);
}

__device__ __forceinline__ float gelu_tanh(float x) {
    const float k0 = 0.7978845608028654f;
    const float k1 = 0.044715f;
    float u = k0 * (x + k1 * x * x * x);
    float t = __expf(2.0f * u);
    float th = (t - 1.0f) / (t + 1.0f);
    return 0.5f * x * (1.0f + th);
}

// -------- fp16 tensor-core GEMM: C = A[M,K]*W[N,K]^T + bias -------
// 128x128x32 tile, 256 threads, warp grid 2(m)x4(n), warp tile 64x32.
// fp16 m16n8k16 MMA, 3-stage cp.async, one sync per k-tile, 2 CTAs/SM.
#define HST 40                  // smem row stride in halfs (80B; bank-clean)
#define HBUF (128 * HST)        // halfs per matrix stage

__global__ __launch_bounds__(256, 2)
void gemm_f16(const __half* __restrict__ A, const __half* __restrict__ W,
              const float* __restrict__ bias, const float* __restrict__ resid,
              void* __restrict__ Cv, int M, int N, int K,
              int act, int outHalf, int rnd) {
    extern __shared__ __half hsm[];
    __half* As = hsm;                   // [3][128][40]
    __half* Ws = hsm + 3 * HBUF;        // [3][128][40]

    int tid = threadIdx.x;
    int warp = tid >> 5, lane = tid & 31;
    int wm = warp >> 2, wn = warp & 3;
    int g = lane >> 2, tig = lane & 3;
    int rowBase = blockIdx.y * 128, colBase = blockIdx.x * 128;
    const __half* Ap = A + (size_t)rowBase * K;
    const __half* Wp = W + (size_t)colBase * K;

    float acc[4][4][4];
#pragma unroll
    for (int i = 0; i < 4; i++)
#pragma unroll
        for (int j = 0; j < 4; j++)
#pragma unroll
            for (int p = 0; p < 4; p++) acc[i][j][p] = 0.f;

    // loader: 128 rows x 4 chunks (16B = 8 halfs) per matrix; 2 iters
    int lr = tid >> 1;                 // (with i*256: covers 0..511)
    // use idx mapping below instead

    // prologue: stage tiles 0 and 1
#pragma unroll
    for (int pt = 0; pt < 2; pt++) {
        int kt = pt * 32;
#pragma unroll
        for (int i = 0; i < 2; i++) {
            int idx = tid + i * 256;        // 0..511
            int r = idx >> 2, c4 = idx & 3;
            cp16(&As[pt * HBUF + r * HST + c4 * 8], Ap + (size_t)r * K + kt + c4 * 8);
            cp16(&Ws[pt * HBUF + r * HST + c4 * 8], Wp + (size_t)r * K + kt + c4 * 8);
        }
        CP_COMMIT();
    }
    (void)lr;

    int nt = K >> 5;
    int buf = 0;
    for (int t = 0; t < nt; t++) {
        if (t == nt - 1) asm volatile("cp.async.wait_group 0;" ::: "memory");
        else             asm volatile("cp.async.wait_group 1;" ::: "memory");
        __syncthreads();
        if (t + 2 < nt) {
            int kt = (t + 2) * 32;
            int nb = buf >= 1 ? buf - 1 : buf + 2;   // (t+2)%3
#pragma unroll
            for (int i = 0; i < 2; i++) {
                int idx = tid + i * 256;
                int r = idx >> 2, c4 = idx & 3;
                cp16(&As[nb * HBUF + r * HST + c4 * 8], Ap + (size_t)r * K + kt + c4 * 8);
                cp16(&Ws[nb * HBUF + r * HST + c4 * 8], Wp + (size_t)r * K + kt + c4 * 8);
            }
            CP_COMMIT();
        }
        const __half* Ab = As + buf * HBUF;
        const __half* Wb = Ws + buf * HBUF;
#pragma unroll
        for (int ks = 0; ks < 2; ks++) {          // 2 x k16
            int k0 = ks * 16;
            unsigned af[4][4], bf[4][2];
#pragma unroll
            for (int mi = 0; mi < 4; mi++) {
                int r0 = wm * 64 + mi * 16 + g;
                af[mi][0] = *(const unsigned*)&Ab[r0 * HST + k0 + 2 * tig];
                af[mi][1] = *(const unsigned*)&Ab[(r0 + 8) * HST + k0 + 2 * tig];
                af[mi][2] = *(const unsigned*)&Ab[r0 * HST + k0 + 8 + 2 * tig];
                af[mi][3] = *(const unsigned*)&Ab[(r0 + 8) * HST + k0 + 8 + 2 * tig];
            }
#pragma unroll
            for (int nj = 0; nj < 4; nj++) {
                int c0 = wn * 32 + nj * 8 + g;
                bf[nj][0] = *(const unsigned*)&Wb[c0 * HST + k0 + 2 * tig];
                bf[nj][1] = *(const unsigned*)&Wb[c0 * HST + k0 + 8 + 2 * tig];
            }
#pragma unroll
            for (int mi = 0; mi < 4; mi++)
#pragma unroll
                for (int nj = 0; nj < 4; nj++)
                    mma_f16(acc[mi][nj], af[mi], bf[nj]);
        }
        buf = buf < 2 ? buf + 1 : 0;
    }

    // epilogue
    float* Cf = (float*)Cv;
    __half* Ch = (__half*)Cv;
#pragma unroll
    for (int mi = 0; mi < 4; mi++) {
#pragma unroll
        for (int h2 = 0; h2 < 2; h2++) {
            int r = rowBase + wm * 64 + mi * 16 + g + h2 * 8;
            const float* rrow = resid ? resid + (size_t)r * N : nullptr;
#pragma unroll
            for (int nj = 0; nj < 4; nj++) {
                int c = colBase + wn * 32 + nj * 8 + 2 * tig;
                float v0 = acc[mi][nj][h2 * 2]     + bias[c];
                float v1 = acc[mi][nj][h2 * 2 + 1] + bias[c + 1];
                if (act == 1) { v0 = gelu_tanh(v0); v1 = gelu_tanh(v1); }
                if (rrow) { v0 += rrow[c]; v1 += rrow[c + 1]; }
                if (outHalf) {
                    *(__half2*)&Ch[(size_t)r * N + c] = __floats2half2_rn(v0, v1);
                } else {
                    if (rnd) { v0 = rtf(v0); v1 = rtf(v1); }
                    *(float2*)&Cf[(size_t)r * N + c] = make_float2(v0, v1);
                }
            }
        }
    }
}

// -------- Flash attention: 128q x 64k tiles, per-warp pipeline -----
// (unchanged tf32 path; y output now fp16)
#define QS 68
#define VSS 72
#define KB1 (64 * QS)
#define VB1 (64 * VSS)

__global__ __launch_bounds__(256, 2)
void flash_attn_tc(const float* __restrict__ qkv, __half* __restrict__ y) {
    extern __shared__ float smf[];
    float* Ks = smf;                  // [2][64][68]
    float* Vs = Ks + 2 * KB1;         // [2][64][72]
    float* Ps = Vs + 2 * VB1;         // [128][68]  Q staging, then P probs
    float* hrow = Ps + 128 * QS;      // [128]

    int tid = threadIdx.x;
    int warp = tid >> 5, lane = tid & 31;
    int g = lane >> 2, tig = lane & 3;
    int qt = (TDIM / 128 - 1) - blockIdx.x;   // long tiles first
    int bh = blockIdx.y;
    int b = bh >> 4, h = bh & 15;
    int qb = qt * 128;
    const float* base = qkv + (size_t)b * TDIM * QKVC + h * HD;

    // prefetch Q (128x64 -> Ps) + K0 + V0
#pragma unroll
    for (int i = 0; i < 8; i++) {
        int ch = tid + i * 256; int r = ch >> 4; int c = (ch & 15) * 4;
        cp16(&Ps[r * QS + c], &base[(size_t)(qb + r) * QKVC + c]);
    }
#pragma unroll
    for (int i = 0; i < 4; i++) {
        int ch = tid + i * 256; int r = ch >> 4; int c = (ch & 15) * 4;
        cp16(&Ks[r * QS + c], &base[(size_t)r * QKVC + CDIM + c]);
        cp16(&Vs[r * VSS + c], &base[(size_t)r * QKVC + 2 * CDIM + c]);
    }
    CP_COMMIT();
    CP_WAIT0();
    __syncthreads();

    // hoist Q fragments (warp's 16 rows x 64 d)
    int r0l = warp * 16 + g;
    unsigned qf[8][4];
#pragma unroll
    for (int ks = 0; ks < 8; ks++) {
        qf[ks][0] = __float_as_uint(Ps[r0l * QS + ks * 8 + tig]);
        qf[ks][1] = __float_as_uint(Ps[(r0l + 8) * QS + ks * 8 + tig]);
        qf[ks][2] = __float_as_uint(Ps[r0l * QS + ks * 8 + tig + 4]);
        qf[ks][3] = __float_as_uint(Ps[(r0l + 8) * QS + ks * 8 + tig + 4]);
    }

    float m0 = NEG_BIG, m1 = NEG_BIG, l0 = 0.f, l1 = 0.f, w0 = 0.f, w1 = 0.f;
    float oacc[8][4];
#pragma unroll
    for (int nj = 0; nj < 8; nj++)
#pragma unroll
        for (int p = 0; p < 4; p++) oacc[nj][p] = 0.f;

    int row0 = qb + warp * 16 + g, row1 = row0 + 8;
    int ni = 2 * qt + 2;

    for (int i = 0; i < ni; i++) {
        CP_WAIT0();
        __syncthreads();
        if (i + 1 < ni) {
            int nb = (i + 1) & 1, kb2 = (i + 1) * 64;
#pragma unroll
            for (int it = 0; it < 4; it++) {
                int ch = tid + it * 256; int r = ch >> 4; int c = (ch & 15) * 4;
                cp16(&Ks[nb * KB1 + r * QS + c],
                     &base[(size_t)(kb2 + r) * QKVC + CDIM + c]);
                cp16(&Vs[nb * VB1 + r * VSS + c],
                     &base[(size_t)(kb2 + r) * QKVC + 2 * CDIM + c]);
            }
            CP_COMMIT();
        }
        int kb = i * 64;
        if (qb + warp * 16 + 15 >= kb) {   // warp has unmasked rows here
            const float* Kb = Ks + (i & 1) * KB1;
            const float* Vb = Vs + (i & 1) * VB1;

            // ---- S = Q K^T (registers) ----
            float sacc[8][4];
#pragma unroll
            for (int nj = 0; nj < 8; nj++)
#pragma unroll
                for (int p = 0; p < 4; p++) sacc[nj][p] = 0.f;
#pragma unroll
            for (int ks = 0; ks < 8; ks++) {
#pragma unroll
                for (int nj = 0; nj < 8; nj++) {
                    int c0 = nj * 8 + g;
                    unsigned bf[2];
                    bf[0] = __float_as_uint(Kb[c0 * QS + ks * 8 + tig]);
                    bf[1] = __float_as_uint(Kb[c0 * QS + ks * 8 + tig + 4]);
                    mma_tf32(sacc[nj], qf[ks], bf);
                }
            }

            // ---- scale + mask + row max ----
            float mx0 = NEG_BIG, mx1 = NEG_BIG;
#pragma unroll
            for (int nj = 0; nj < 8; nj++) {
                int cg = kb + nj * 8 + 2 * tig;
                float s0 = sacc[nj][0] * 0.125f;
                float s1 = sacc[nj][1] * 0.125f;
                float s2 = sacc[nj][2] * 0.125f;
                float s3 = sacc[nj][3] * 0.125f;
                if (cg > row0) s0 = NEG_BIG;
                if (cg + 1 > row0) s1 = NEG_BIG;
                if (cg > row1) s2 = NEG_BIG;
                if (cg + 1 > row1) s3 = NEG_BIG;
                sacc[nj][0] = s0; sacc[nj][1] = s1;
                sacc[nj][2] = s2; sacc[nj][3] = s3;
                mx0 = fmaxf(mx0, fmaxf(s0, s1));
                mx1 = fmaxf(mx1, fmaxf(s2, s3));
            }
            mx0 = fmaxf(mx0, __shfl_xor_sync(0xFFFFFFFFu, mx0, 1));
            mx0 = fmaxf(mx0, __shfl_xor_sync(0xFFFFFFFFu, mx0, 2));
            mx1 = fmaxf(mx1, __shfl_xor_sync(0xFFFFFFFFu, mx1, 1));
            mx1 = fmaxf(mx1, __shfl_xor_sync(0xFFFFFFFFu, mx1, 2));
            float mn0 = fmaxf(m0, mx0), mn1 = fmaxf(m1, mx1);

            // ---- exp + sums + write P ----
            float se0 = 0.f, se1 = 0.f, sw0 = 0.f, sw1 = 0.f;
#pragma unroll
            for (int nj = 0; nj < 8; nj++) {
                float s0 = sacc[nj][0], s1 = sacc[nj][1];
                float s2 = sacc[nj][2], s3 = sacc[nj][3];
                float e0 = __expf(s0 - mn0), e1 = __expf(s1 - mn0);
                float e2 = __expf(s2 - mn1), e3 = __expf(s3 - mn1);
                se0 += e0 + e1; sw0 += e0 * s0 + e1 * s1;
                se1 += e2 + e3; sw1 += e2 * s2 + e3 * s3;
                int c0 = nj * 8 + 2 * tig;
                *(float2*)&Ps[(warp * 16 + g) * QS + c0] =
                    make_float2(rtf(e0), rtf(e1));
                *(float2*)&Ps[(warp * 16 + g + 8) * QS + c0] =
                    make_float2(rtf(e2), rtf(e3));
            }
            se0 += __shfl_xor_sync(0xFFFFFFFFu, se0, 1);
            se0 += __shfl_xor_sync(0xFFFFFFFFu, se0, 2);
            sw0 += __shfl_xor_sync(0xFFFFFFFFu, sw0, 1);
            sw0 += __shfl_xor_sync(0xFFFFFFFFu, sw0, 2);
            se1 += __shfl_xor_sync(0xFFFFFFFFu, se1, 1);
            se1 += __shfl_xor_sync(0xFFFFFFFFu, se1, 2);
            sw1 += __shfl_xor_sync(0xFFFFFFFFu, sw1, 1);
            sw1 += __shfl_xor_sync(0xFFFFFFFFu, sw1, 2);

            float c0f = __expf(m0 - mn0), c1f = __expf(m1 - mn1);
            l0 = l0 * c0f + se0; w0 = w0 * c0f + sw0; m0 = mn0;
            l1 = l1 * c1f + se1; w1 = w1 * c1f + sw1; m1 = mn1;
#pragma unroll
            for (int nj = 0; nj < 8; nj++) {
                oacc[nj][0] *= c0f; oacc[nj][1] *= c0f;
                oacc[nj][2] *= c1f; oacc[nj][3] *= c1f;
            }
            __syncwarp();

            // ---- O += P V ----
#pragma unroll
            for (int ks = 0; ks < 8; ks++) {
                unsigned af[4];
                af[0] = __float_as_uint(Ps[r0l * QS + ks * 8 + tig]);
                af[1] = __float_as_uint(Ps[(r0l + 8) * QS + ks * 8 + tig]);
                af[2] = __float_as_uint(Ps[r0l * QS + ks * 8 + tig + 4]);
                af[3] = __float_as_uint(Ps[(r0l + 8) * QS + ks * 8 + tig + 4]);
#pragma unroll
                for (int nj = 0; nj < 8; nj++) {
                    int d0 = nj * 8 + g;
                    unsigned bf[2];
                    bf[0] = __float_as_uint(Vb[(ks * 8 + tig) * VSS + d0]);
                    bf[1] = __float_as_uint(Vb[(ks * 8 + tig + 4) * VSS + d0]);
                    mma_tf32(oacc[nj], af, bf);
                }
            }
            __syncwarp();
        }
    }

    // write O (divide by l) as fp16 (attnproj A operand)
    {
        float li0 = 1.0f / l0, li1 = 1.0f / l1;
#pragma unroll
        for (int nj = 0; nj < 8; nj++) {
            int c = h * HD + nj * 8 + 2 * tig;
            *(__half2*)&y[(size_t)(b * TDIM + row0) * CDIM + c] =
                __floats2half2_rn(oacc[nj][0] * li0, oacc[nj][1] * li0);
            *(__half2*)&y[(size_t)(b * TDIM + row1) * CDIM + c] =
                __floats2half2_rn(oacc[nj][2] * li1, oacc[nj][3] * li1);
        }
    }

    // entropy: H_row = m + log(S) - W/S
    if (tig == 0) {
        hrow[warp * 16 + g]     = m0 + logf(l0) - w0 / l0;
        hrow[warp * 16 + g + 8] = m1 + logf(l1) - w1 / l1;
    }
    __syncthreads();
    if (tid == 0) {
        float tot = 0.f;
        for (int i = 0; i < 128; i++) tot += hrow[i];
        atomicAdd(&g_ent, tot);
    }
}

// ------------------------------------------------------------------
extern "C" void kernel_launch(void* const* d_in, const int* in_sizes, int n_in,
                              void* d_out, int out_size) {
    const float* x          = (const float*)d_in[0];
    const float* ln1_w      = (const float*)d_in[1];
    const float* ln1_b      = (const float*)d_in[2];
    const float* attn_w     = (const float*)d_in[3];
    const float* attn_b     = (const float*)d_in[4];
    const float* attnproj_w = (const float*)d_in[5];
    const float* attnproj_b = (const float*)d_in[6];
    const float* ln2_w      = (const float*)d_in[7];
    const float* ln2_b      = (const float*)d_in[8];
    const float* fc_w       = (const float*)d_in[9];
    const float* fc_b       = (const float*)d_in[10];
    const float* proj_w     = (const float*)d_in[11];
    const float* proj_b     = (const float*)d_in[12];
    float* out = (float*)d_out;

    __half *p_h, *p_y, *p_m, *p_wh;
    float *p_qkv, *p_x1;
    cudaGetSymbolAddress((void**)&p_h,   g_h);
    cudaGetSymbolAddress((void**)&p_qkv, g_qkv);
    cudaGetSymbolAddress((void**)&p_y,   g_y);
    cudaGetSymbolAddress((void**)&p_x1,  g_x1);
    cudaGetSymbolAddress((void**)&p_m,   g_m);
    cudaGetSymbolAddress((void**)&p_wh,  g_wh);

    static int gemm_smem = 6 * HBUF * 2;                             // 61440 B
    static int attn_smem = (2 * KB1 + 2 * VB1 + 128 * QS + 128) * 4; // ~107 KB
    cudaFuncSetAttribute(gemm_f16,
                         cudaFuncAttributeMaxDynamicSharedMemorySize, gemm_smem);
    cudaFuncSetAttribute(flash_attn_tc,
                         cudaFuncAttributeMaxDynamicSharedMemorySize, attn_smem);

    zero_ent_kernel<<<1, 1>>>();

    // RN-convert weights to fp16 once per launch
    tohalf_kernel<<<3145728 / 1024, 256>>>(attn_w,     p_wh + WR_ATTN,  3145728);
    tohalf_kernel<<<1048576 / 1024, 256>>>(attnproj_w, p_wh + WR_APROJ, 1048576);
    tohalf_kernel<<<4194304 / 1024, 256>>>(fc_w,       p_wh + WR_FC,    4194304);
    tohalf_kernel<<<4194304 / 1024, 256>>>(proj_w,     p_wh + WR_PROJ,  4194304);

    // h = LN1(x)  (fp16 out)
    ln_kernel<<<BT, 256>>>(x, ln1_w, ln1_b, p_h);

    // qkv = h @ attn_w^T + attn_b   (fp32 out, tf32-rounded -> attention)
    gemm_f16<<<dim3(QKVC / 128, BT / 128), 256, gemm_smem>>>(
        p_h, p_wh + WR_ATTN, attn_b, nullptr, p_qkv, BT, QKVC, CDIM, 0, 0, 1);

    // attention (+entropy) -> y fp16
    flash_attn_tc<<<dim3(TDIM / 128, BH), 256, attn_smem>>>(p_qkv, p_y);

    // x1 = x + y @ attnproj_w^T + attnproj_b   (fp32 out)
    gemm_f16<<<dim3(CDIM / 128, BT / 128), 256, gemm_smem>>>(
        p_y, p_wh + WR_APROJ, attnproj_b, x, p_x1, BT, CDIM, CDIM, 0, 0, 0);

    // h = LN2(x1)  (fp16 out)
    ln_kernel<<<BT, 256>>>(p_x1, ln2_w, ln2_b, p_h);

    // m = gelu(h @ fc_w^T + fc_b)   (fp16 out)
    gemm_f16<<<dim3(FFC / 128, BT / 128), 256, gemm_smem>>>(
        p_h, p_wh + WR_FC, fc_b, nullptr, p_m, BT, FFC, CDIM, 1, 1, 0);

    // out = x1 + m @ proj_w^T + proj_b   (fp32 out)
    gemm_f16<<<dim3(CDIM / 128, BT / 128), 256, gemm_smem>>>(
        p_m, p_wh + WR_PROJ, proj_b, p_x1, out, BT, CDIM, FFC, 0, 0, 0);

    // entropy scalar
    finalize_kernel<<<1, 1>>>(out, out_size);
}

// round 12
// speedup vs baseline: 1.7282x; 1.1659x over previous
#include <cuda_runtime.h>
#include <cuda_fp16.h>
#include <math.h>
#include <stdint.h>

// Problem constants
#define BATCH 2
#define TDIM 2048
#define CDIM 1024
#define HN 16
#define HD 64
#define BT (BATCH * TDIM)        // 4096 rows
#define BH (BATCH * HN)          // 32 batch-heads
#define QKVC (3 * CDIM)          // 3072
#define FFC (4 * CDIM)           // 4096

#define NEG_BIG (-1e30f)

// -------- scratch (static device globals; no allocation) ----------
__device__ __half g_h[BT * CDIM];      // LN output (GEMM A operand)
__device__ __half g_qkv[BT * QKVC];    // qkv fp16 (attention operand)
__device__ __half g_y[BT * CDIM];      // attention out (attnproj A operand)
__device__ float  g_x1[BT * CDIM];     // x + attn (fp32 residual)
__device__ __half g_m[BT * FFC];       // gelu(fc) (proj A operand)
__device__ __half g_wh[12582912];      // fp16 weights: attn|attnproj|fc|proj
__device__ float  g_ent;

#define WR_ATTN  0
#define WR_APROJ 3145728
#define WR_FC    4194304
#define WR_PROJ  8388608

// ------------------------------------------------------------------
__global__ void zero_ent_kernel() { g_ent = 0.0f; }

__global__ void finalize_kernel(float* out, int out_size) {
    if (out_size > BT * CDIM)
        out[BT * CDIM] = g_ent * (1.0f / (float)(BH * TDIM));
}

// -------- helpers -------------------------------------------------
__device__ __forceinline__ void cp16(void* s, const void* g) {
    unsigned sa = (unsigned)__cvta_generic_to_shared(s);
    asm volatile("cp.async.cg.shared.global [%0], [%1], 16;" :: "r"(sa), "l"(g));
}
#define CP_COMMIT() asm volatile("cp.async.commit_group;")
#define CP_WAIT0()  asm volatile("cp.async.wait_group 0;")

__device__ __forceinline__ void mma_f16(float* c, const unsigned* a, const unsigned* b) {
    asm("mma.sync.aligned.m16n8k16.row.col.f32.f16.f16.f32 "
        "{%0,%1,%2,%3}, {%4,%5,%6,%7}, {%8,%9}, {%0,%1,%2,%3};"
        : "+f"(c[0]), "+f"(c[1]), "+f"(c[2]), "+f"(c[3])
        : "r"(a[0]), "r"(a[1]), "r"(a[2]), "r"(a[3]), "r"(b[0]), "r"(b[1]));
}

__device__ __forceinline__ unsigned pack_h2(float a, float b) {
    __half2 h = __floats2half2_rn(a, b);
    return *(unsigned*)&h;
}

// -------- weight conversion fp32 -> fp16 (RN) ---------------------
__global__ void tohalf_kernel(const float* __restrict__ in,
                              __half* __restrict__ out, int n) {
    int i = (blockIdx.x * blockDim.x + threadIdx.x) * 4;
    if (i < n) {
        float4 v = *(const float4*)&in[i];
        *(__half2*)&out[i]     = __floats2half2_rn(v.x, v.y);
        *(__half2*)&out[i + 2] = __floats2half2_rn(v.z, v.w);
    }
}

// -------- LayerNorm: fp32 in, fp16 out ----------------------------
__global__ void ln_kernel(const float* __restrict__ x,
                          const float* __restrict__ w,
                          const float* __restrict__ b,
                          __half* __restrict__ out) {
    int row = blockIdx.x;
    int tid = threadIdx.x;
    int lane = tid & 31, warp = tid >> 5;
    const float* xr = x + (size_t)row * CDIM;
    __shared__ float rs[8], rq[8];

    float4 v = *(const float4*)&xr[tid * 4];
    float lsum = v.x + v.y + v.z + v.w;
    float lsq  = v.x * v.x + v.y * v.y + v.z * v.z + v.w * v.w;
#pragma unroll
    for (int o = 16; o > 0; o >>= 1) {
        lsum += __shfl_xor_sync(0xFFFFFFFFu, lsum, o);
        lsq  += __shfl_xor_sync(0xFFFFFFFFu, lsq, o);
    }
    if (lane == 0) { rs[warp] = lsum; rq[warp] = lsq; }
    __syncthreads();
    float tsum, tsq;
    {
        float a = rs[lane & 7], c = rq[lane & 7];
#pragma unroll
        for (int o = 4; o > 0; o >>= 1) {
            a += __shfl_xor_sync(0xFFFFFFFFu, a, o);
            c += __shfl_xor_sync(0xFFFFFFFFu, c, o);
        }
        tsum = a; tsq = c;
    }
    float mean = tsum * (1.0f / CDIM);
    float var = tsq * (1.0f / CDIM) - mean * mean;
    float rstd = rsqrtf(var + 1e-5f);

    float4 wv = *(const float4*)&w[tid * 4];
    float4 bv = *(const float4*)&b[tid * 4];
    __half2* orow = (__half2*)(out + (size_t)row * CDIM);
    orow[tid * 2] = __floats2half2_rn((v.x - mean) * rstd * wv.x + bv.x,
                                      (v.y - mean) * rstd * wv.y + bv.y);
    orow[tid * 2 + 1] = __floats2half2_rn((v.z - mean) * rstd * wv.z + bv.z,
                                          (v.w - mean) * rstd * wv.w + bv.w);
}

__device__ __forceinline__ float gelu_tanh(float x) {
    const float k0 = 0.7978845608028654f;
    const float k1 = 0.044715f;
    float u = k0 * (x + k1 * x * x * x);
    float t = __expf(2.0f * u);
    float th = (t - 1.0f) / (t + 1.0f);
    return 0.5f * x * (1.0f + th);
}

// -------- fp16 tensor-core GEMM: C = A[M,K]*W[N,K]^T + bias -------
// 128x128x32 tile, 256 threads, warp grid 2(m)x4(n), warp tile 64x32.
#define HST 40                  // smem row stride in halfs (80B)
#define HBUF (128 * HST)

__global__ __launch_bounds__(256, 2)
void gemm_f16(const __half* __restrict__ A, const __half* __restrict__ W,
              const float* __restrict__ bias, const float* __restrict__ resid,
              void* __restrict__ Cv, int M, int N, int K,
              int act, int outHalf) {
    extern __shared__ __half hsm[];
    __half* As = hsm;                   // [3][128][40]
    __half* Ws = hsm + 3 * HBUF;        // [3][128][40]

    int tid = threadIdx.x;
    int warp = tid >> 5, lane = tid & 31;
    int wm = warp >> 2, wn = warp & 3;
    int g = lane >> 2, tig = lane & 3;
    int rowBase = blockIdx.y * 128, colBase = blockIdx.x * 128;
    const __half* Ap = A + (size_t)rowBase * K;
    const __half* Wp = W + (size_t)colBase * K;

    float acc[4][4][4];
#pragma unroll
    for (int i = 0; i < 4; i++)
#pragma unroll
        for (int j = 0; j < 4; j++)
#pragma unroll
            for (int p = 0; p < 4; p++) acc[i][j][p] = 0.f;

    // prologue: stage tiles 0 and 1
#pragma unroll
    for (int pt = 0; pt < 2; pt++) {
        int kt = pt * 32;
#pragma unroll
        for (int i = 0; i < 2; i++) {
            int idx = tid + i * 256;
            int r = idx >> 2, c4 = idx & 3;
            cp16(&As[pt * HBUF + r * HST + c4 * 8], Ap + (size_t)r * K + kt + c4 * 8);
            cp16(&Ws[pt * HBUF + r * HST + c4 * 8], Wp + (size_t)r * K + kt + c4 * 8);
        }
        CP_COMMIT();
    }

    int nt = K >> 5;
    int buf = 0;
    for (int t = 0; t < nt; t++) {
        if (t == nt - 1) asm volatile("cp.async.wait_group 0;" ::: "memory");
        else             asm volatile("cp.async.wait_group 1;" ::: "memory");
        __syncthreads();
        if (t + 2 < nt) {
            int kt = (t + 2) * 32;
            int nb = buf >= 1 ? buf - 1 : buf + 2;   // (t+2)%3
#pragma unroll
            for (int i = 0; i < 2; i++) {
                int idx = tid + i * 256;
                int r = idx >> 2, c4 = idx & 3;
                cp16(&As[nb * HBUF + r * HST + c4 * 8], Ap + (size_t)r * K + kt + c4 * 8);
                cp16(&Ws[nb * HBUF + r * HST + c4 * 8], Wp + (size_t)r * K + kt + c4 * 8);
            }
            CP_COMMIT();
        }
        const __half* Ab = As + buf * HBUF;
        const __half* Wb = Ws + buf * HBUF;
#pragma unroll
        for (int ks = 0; ks < 2; ks++) {
            int k0 = ks * 16;
            unsigned af[4][4], bf[4][2];
#pragma unroll
            for (int mi = 0; mi < 4; mi++) {
                int r0 = wm * 64 + mi * 16 + g;
                af[mi][0] = *(const unsigned*)&Ab[r0 * HST + k0 + 2 * tig];
                af[mi][1] = *(const unsigned*)&Ab[(r0 + 8) * HST + k0 + 2 * tig];
                af[mi][2] = *(const unsigned*)&Ab[r0 * HST + k0 + 8 + 2 * tig];
                af[mi][3] = *(const unsigned*)&Ab[(r0 + 8) * HST + k0 + 8 + 2 * tig];
            }
#pragma unroll
            for (int nj = 0; nj < 4; nj++) {
                int c0 = wn * 32 + nj * 8 + g;
                bf[nj][0] = *(const unsigned*)&Wb[c0 * HST + k0 + 2 * tig];
                bf[nj][1] = *(const unsigned*)&Wb[c0 * HST + k0 + 8 + 2 * tig];
            }
#pragma unroll
            for (int mi = 0; mi < 4; mi++)
#pragma unroll
                for (int nj = 0; nj < 4; nj++)
                    mma_f16(acc[mi][nj], af[mi], bf[nj]);
        }
        buf = buf < 2 ? buf + 1 : 0;
    }

    // epilogue
    float* Cf = (float*)Cv;
    __half* Ch = (__half*)Cv;
#pragma unroll
    for (int mi = 0; mi < 4; mi++) {
#pragma unroll
        for (int h2 = 0; h2 < 2; h2++) {
            int r = rowBase + wm * 64 + mi * 16 + g + h2 * 8;
            const float* rrow = resid ? resid + (size_t)r * N : nullptr;
#pragma unroll
            for (int nj = 0; nj < 4; nj++) {
                int c = colBase + wn * 32 + nj * 8 + 2 * tig;
                float v0 = acc[mi][nj][h2 * 2]     + bias[c];
                float v1 = acc[mi][nj][h2 * 2 + 1] + bias[c + 1];
                if (act == 1) { v0 = gelu_tanh(v0); v1 = gelu_tanh(v1); }
                if (rrow) { v0 += rrow[c]; v1 += rrow[c + 1]; }
                if (outHalf) {
                    *(__half2*)&Ch[(size_t)r * N + c] = __floats2half2_rn(v0, v1);
                } else {
                    *(float2*)&Cf[(size_t)r * N + c] = make_float2(v0, v1);
                }
            }
        }
    }
}

// -------- fp16 flash attention: 128q x 64k tiles -------------------
// P stays in registers (softmax layout == m16n8k16 A-frag layout);
// V fragments via ldmatrix.x4.trans.
#define AST 72                  // halfs stride (144B)
#define KVN (64 * AST)          // halfs per K or V buffer

__global__ __launch_bounds__(256, 2)
void flash_attn_f16(const __half* __restrict__ qkv, __half* __restrict__ y) {
    extern __shared__ __half hs[];
    __half* Qs = hs;                     // [128][72]
    __half* Ks = Qs + 128 * AST;         // [2][64][72]
    __half* Vs = Ks + 2 * KVN;           // [2][64][72]
    float* hrow = (float*)(Vs + 2 * KVN);// [128]

    int tid = threadIdx.x;
    int warp = tid >> 5, lane = tid & 31;
    int g = lane >> 2, tig = lane & 3;
    int qt = (TDIM / 128 - 1) - blockIdx.x;   // long tiles first
    int bh = blockIdx.y;
    int b = bh >> 4, h = bh & 15;
    int qb = qt * 128;
    const __half* base = qkv + (size_t)b * TDIM * QKVC + h * HD;

    // prefetch Q (128x64) + K0 + V0
#pragma unroll
    for (int i = 0; i < 4; i++) {
        int idx = tid + i * 256;           // 0..1023
        int r = idx >> 3, c = (idx & 7) * 8;
        cp16(&Qs[r * AST + c], &base[(size_t)(qb + r) * QKVC + c]);
    }
#pragma unroll
    for (int i = 0; i < 2; i++) {
        int idx = tid + i * 256;           // 0..511
        int r = idx >> 3, c = (idx & 7) * 8;
        cp16(&Ks[r * AST + c], &base[(size_t)r * QKVC + CDIM + c]);
        cp16(&Vs[r * AST + c], &base[(size_t)r * QKVC + 2 * CDIM + c]);
    }
    CP_COMMIT();
    CP_WAIT0();
    __syncthreads();

    // hoist Q fragments: warp's 16 rows x 64 d = 4 k16-steps
    int r0l = warp * 16 + g;
    unsigned qf[4][4];
#pragma unroll
    for (int ks = 0; ks < 4; ks++) {
        qf[ks][0] = *(const unsigned*)&Qs[r0l * AST + ks * 16 + 2 * tig];
        qf[ks][1] = *(const unsigned*)&Qs[(r0l + 8) * AST + ks * 16 + 2 * tig];
        qf[ks][2] = *(const unsigned*)&Qs[r0l * AST + ks * 16 + 8 + 2 * tig];
        qf[ks][3] = *(const unsigned*)&Qs[(r0l + 8) * AST + ks * 16 + 8 + 2 * tig];
    }

    uint32_t vs_u32 = (uint32_t)__cvta_generic_to_shared(Vs);
    uint32_t lm_off = (uint32_t)(((lane & 15) * AST + (lane >> 4) * 8) * 2);

    float m0 = NEG_BIG, m1 = NEG_BIG, l0 = 0.f, l1 = 0.f, w0 = 0.f, w1 = 0.f;
    float oacc[8][4];
#pragma unroll
    for (int nj = 0; nj < 8; nj++)
#pragma unroll
        for (int p = 0; p < 4; p++) oacc[nj][p] = 0.f;

    int row0 = qb + warp * 16 + g, row1 = row0 + 8;
    int ni = 2 * qt + 2;

    for (int i = 0; i < ni; i++) {
        CP_WAIT0();
        __syncthreads();
        if (i + 1 < ni) {
            int nb = (i + 1) & 1, kb2 = (i + 1) * 64;
#pragma unroll
            for (int it = 0; it < 2; it++) {
                int idx = tid + it * 256;
                int r = idx >> 3, c = (idx & 7) * 8;
                cp16(&Ks[nb * KVN + r * AST + c],
                     &base[(size_t)(kb2 + r) * QKVC + CDIM + c]);
                cp16(&Vs[nb * KVN + r * AST + c],
                     &base[(size_t)(kb2 + r) * QKVC + 2 * CDIM + c]);
            }
            CP_COMMIT();
        }
        int kb = i * 64;
        if (qb + warp * 16 + 15 >= kb) {   // warp has unmasked rows here
            const __half* Kb = Ks + (i & 1) * KVN;

            // ---- S = Q K^T (fp16 MMA, fp32 accum) ----
            float sacc[8][4];
#pragma unroll
            for (int nj = 0; nj < 8; nj++)
#pragma unroll
                for (int p = 0; p < 4; p++) sacc[nj][p] = 0.f;
#pragma unroll
            for (int ks = 0; ks < 4; ks++) {
#pragma unroll
                for (int nj = 0; nj < 8; nj++) {
                    int c0 = nj * 8 + g;
                    unsigned bf[2];
                    bf[0] = *(const unsigned*)&Kb[c0 * AST + ks * 16 + 2 * tig];
                    bf[1] = *(const unsigned*)&Kb[c0 * AST + ks * 16 + 8 + 2 * tig];
                    mma_f16(sacc[nj], qf[ks], bf);
                }
            }

            // ---- scale + mask + row max ----
            float mx0 = NEG_BIG, mx1 = NEG_BIG;
#pragma unroll
            for (int nj = 0; nj < 8; nj++) {
                int cg = kb + nj * 8 + 2 * tig;
                float s0 = sacc[nj][0] * 0.125f;
                float s1 = sacc[nj][1] * 0.125f;
                float s2 = sacc[nj][2] * 0.125f;
                float s3 = sacc[nj][3] * 0.125f;
                if (cg > row0) s0 = NEG_BIG;
                if (cg + 1 > row0) s1 = NEG_BIG;
                if (cg > row1) s2 = NEG_BIG;
                if (cg + 1 > row1) s3 = NEG_BIG;
                sacc[nj][0] = s0; sacc[nj][1] = s1;
                sacc[nj][2] = s2; sacc[nj][3] = s3;
                mx0 = fmaxf(mx0, fmaxf(s0, s1));
                mx1 = fmaxf(mx1, fmaxf(s2, s3));
            }
            mx0 = fmaxf(mx0, __shfl_xor_sync(0xFFFFFFFFu, mx0, 1));
            mx0 = fmaxf(mx0, __shfl_xor_sync(0xFFFFFFFFu, mx0, 2));
            mx1 = fmaxf(mx1, __shfl_xor_sync(0xFFFFFFFFu, mx1, 1));
            mx1 = fmaxf(mx1, __shfl_xor_sync(0xFFFFFFFFu, mx1, 2));
            float mn0 = fmaxf(m0, mx0), mn1 = fmaxf(m1, mx1);

            // ---- exp + sums; P packed to fp16 A-fragments (registers) ----
            unsigned pe[8][2];
            float se0 = 0.f, se1 = 0.f, sw0 = 0.f, sw1 = 0.f;
#pragma unroll
            for (int nj = 0; nj < 8; nj++) {
                float s0 = sacc[nj][0], s1 = sacc[nj][1];
                float s2 = sacc[nj][2], s3 = sacc[nj][3];
                float e0 = __expf(s0 - mn0), e1 = __expf(s1 - mn0);
                float e2 = __expf(s2 - mn1), e3 = __expf(s3 - mn1);
                se0 += e0 + e1; sw0 += e0 * s0 + e1 * s1;
                se1 += e2 + e3; sw1 += e2 * s2 + e3 * s3;
                pe[nj][0] = pack_h2(e0, e1);   // row g
                pe[nj][1] = pack_h2(e2, e3);   // row g+8
            }
            se0 += __shfl_xor_sync(0xFFFFFFFFu, se0, 1);
            se0 += __shfl_xor_sync(0xFFFFFFFFu, se0, 2);
            sw0 += __shfl_xor_sync(0xFFFFFFFFu, sw0, 1);
            sw0 += __shfl_xor_sync(0xFFFFFFFFu, sw0, 2);
            se1 += __shfl_xor_sync(0xFFFFFFFFu, se1, 1);
            se1 += __shfl_xor_sync(0xFFFFFFFFu, se1, 2);
            sw1 += __shfl_xor_sync(0xFFFFFFFFu, sw1, 1);
            sw1 += __shfl_xor_sync(0xFFFFFFFFu, sw1, 2);

            float c0f = __expf(m0 - mn0), c1f = __expf(m1 - mn1);
            l0 = l0 * c0f + se0; w0 = w0 * c0f + sw0; m0 = mn0;
            l1 = l1 * c1f + se1; w1 = w1 * c1f + sw1; m1 = mn1;
#pragma unroll
            for (int nj = 0; nj < 8; nj++) {
                oacc[nj][0] *= c0f; oacc[nj][1] *= c0f;
                oacc[nj][2] *= c1f; oacc[nj][3] *= c1f;
            }

            // ---- O += P V : V fragments via ldmatrix.x4.trans ----
            uint32_t vbase = vs_u32 + (uint32_t)((i & 1) * KVN * 2) + lm_off;
#pragma unroll
            for (int ks = 0; ks < 4; ks++) {
                unsigned af[4] = { pe[2 * ks][0], pe[2 * ks][1],
                                   pe[2 * ks + 1][0], pe[2 * ks + 1][1] };
#pragma unroll
                for (int dj = 0; dj < 4; dj++) {
                    uint32_t addr = vbase + (uint32_t)((ks * 16 * AST + dj * 16) * 2);
                    unsigned v0, v1, v2, v3;
                    asm volatile(
                        "ldmatrix.sync.aligned.m8n8.x4.trans.shared.b16 "
                        "{%0,%1,%2,%3}, [%4];"
                        : "=r"(v0), "=r"(v1), "=r"(v2), "=r"(v3) : "r"(addr));
                    unsigned bfa[2] = {v0, v1};
                    unsigned bfb[2] = {v2, v3};
                    mma_f16(oacc[2 * dj], af, bfa);
                    mma_f16(oacc[2 * dj + 1], af, bfb);
                }
            }
        }
    }

    // write O (divide by l) as fp16 (attnproj A operand)
    {
        float li0 = 1.0f / l0, li1 = 1.0f / l1;
#pragma unroll
        for (int nj = 0; nj < 8; nj++) {
            int c = h * HD + nj * 8 + 2 * tig;
            *(__half2*)&y[(size_t)(b * TDIM + row0) * CDIM + c] =
                __floats2half2_rn(oacc[nj][0] * li0, oacc[nj][1] * li0);
            *(__half2*)&y[(size_t)(b * TDIM + row1) * CDIM + c] =
                __floats2half2_rn(oacc[nj][2] * li1, oacc[nj][3] * li1);
        }
    }

    // entropy: H_row = m + log(S) - W/S
    if (tig == 0) {
        hrow[warp * 16 + g]     = m0 + logf(l0) - w0 / l0;
        hrow[warp * 16 + g + 8] = m1 + logf(l1) - w1 / l1;
    }
    __syncthreads();
    if (tid == 0) {
        float tot = 0.f;
        for (int i = 0; i < 128; i++) tot += hrow[i];
        atomicAdd(&g_ent, tot);
    }
}

// ------------------------------------------------------------------
extern "C" void kernel_launch(void* const* d_in, const int* in_sizes, int n_in,
                              void* d_out, int out_size) {
    const float* x          = (const float*)d_in[0];
    const float* ln1_w      = (const float*)d_in[1];
    const float* ln1_b      = (const float*)d_in[2];
    const float* attn_w     = (const float*)d_in[3];
    const float* attn_b     = (const float*)d_in[4];
    const float* attnproj_w = (const float*)d_in[5];
    const float* attnproj_b = (const float*)d_in[6];
    const float* ln2_w      = (const float*)d_in[7];
    const float* ln2_b      = (const float*)d_in[8];
    const float* fc_w       = (const float*)d_in[9];
    const float* fc_b       = (const float*)d_in[10];
    const float* proj_w     = (const float*)d_in[11];
    const float* proj_b     = (const float*)d_in[12];
    float* out = (float*)d_out;

    __half *p_h, *p_qkv, *p_y, *p_m, *p_wh;
    float *p_x1;
    cudaGetSymbolAddress((void**)&p_h,   g_h);
    cudaGetSymbolAddress((void**)&p_qkv, g_qkv);
    cudaGetSymbolAddress((void**)&p_y,   g_y);
    cudaGetSymbolAddress((void**)&p_x1,  g_x1);
    cudaGetSymbolAddress((void**)&p_m,   g_m);
    cudaGetSymbolAddress((void**)&p_wh,  g_wh);

    static int gemm_smem = 6 * HBUF * 2;                          // 61440 B
    static int attn_smem = (128 * AST + 4 * KVN) * 2 + 128 * 4;   // ~56 KB
    cudaFuncSetAttribute(gemm_f16,
                         cudaFuncAttributeMaxDynamicSharedMemorySize, gemm_smem);
    cudaFuncSetAttribute(flash_attn_f16,
                         cudaFuncAttributeMaxDynamicSharedMemorySize, attn_smem);

    zero_ent_kernel<<<1, 1>>>();

    // RN-convert weights to fp16 once per launch
    tohalf_kernel<<<3145728 / 1024, 256>>>(attn_w,     p_wh + WR_ATTN,  3145728);
    tohalf_kernel<<<1048576 / 1024, 256>>>(attnproj_w, p_wh + WR_APROJ, 1048576);
    tohalf_kernel<<<4194304 / 1024, 256>>>(fc_w,       p_wh + WR_FC,    4194304);
    tohalf_kernel<<<4194304 / 1024, 256>>>(proj_w,     p_wh + WR_PROJ,  4194304);

    // h = LN1(x)  (fp16 out)
    ln_kernel<<<BT, 256>>>(x, ln1_w, ln1_b, p_h);

    // qkv = h @ attn_w^T + attn_b   (fp16 out -> attention operands)
    gemm_f16<<<dim3(QKVC / 128, BT / 128), 256, gemm_smem>>>(
        p_h, p_wh + WR_ATTN, attn_b, nullptr, p_qkv, BT, QKVC, CDIM, 0, 1);

    // attention (+entropy) -> y fp16
    flash_attn_f16<<<dim3(TDIM / 128, BH), 256, attn_smem>>>(p_qkv, p_y);

    // x1 = x + y @ attnproj_w^T + attnproj_b   (fp32 out)
    gemm_f16<<<dim3(CDIM / 128, BT / 128), 256, gemm_smem>>>(
        p_y, p_wh + WR_APROJ, attnproj_b, x, p_x1, BT, CDIM, CDIM, 0, 0);

    // h = LN2(x1)  (fp16 out)
    ln_kernel<<<BT, 256>>>(p_x1, ln2_w, ln2_b, p_h);

    // m = gelu(h @ fc_w^T + fc_b)   (fp16 out)
    gemm_f16<<<dim3(FFC / 128, BT / 128), 256, gemm_smem>>>(
        p_h, p_wh + WR_FC, fc_b, nullptr, p_m, BT, FFC, CDIM, 1, 1);

    // out = x1 + m @ proj_w^T + proj_b   (fp32 out)
    gemm_f16<<<dim3(CDIM / 128, BT / 128), 256, gemm_smem>>>(
        p_m, p_wh + WR_PROJ, proj_b, p_x1, out, BT, CDIM, FFC, 0, 0);

    // entropy scalar
    finalize_kernel<<<1, 1>>>(out, out_size);
}

// round 13
// speedup vs baseline: 1.9005x; 1.0997x over previous
#include <cuda_runtime.h>
#include <cuda_fp16.h>
#include <math.h>
#include <stdint.h>

// Problem constants
#define BATCH 2
#define TDIM 2048
#define CDIM 1024
#define HN 16
#define HD 64
#define BT (BATCH * TDIM)        // 4096 rows
#define BH (BATCH * HN)          // 32 batch-heads
#define QKVC (3 * CDIM)          // 3072
#define FFC (4 * CDIM)           // 4096

#define NEG_BIG (-1e30f)

// -------- scratch (static device globals; no allocation) ----------
__device__ __half g_h[BT * CDIM];      // LN output (GEMM A operand)
__device__ __half g_qkv[BT * QKVC];    // qkv fp16 (attention operand)
__device__ __half g_y[BT * CDIM];      // attention out (attnproj A operand)
__device__ float  g_x1[BT * CDIM];     // x + attn (fp32 residual)
__device__ __half g_m[BT * FFC];       // gelu(fc) (proj A operand)
__device__ __half g_wh[12582912];      // fp16 weights: attn|attnproj|fc|proj
__device__ float  g_ent;

#define WR_ATTN  0
#define WR_APROJ 3145728
#define WR_FC    4194304
#define WR_PROJ  8388608

// ------------------------------------------------------------------
__global__ void zero_ent_kernel() { g_ent = 0.0f; }

__global__ void finalize_kernel(float* out, int out_size) {
    if (out_size > BT * CDIM)
        out[BT * CDIM] = g_ent * (1.0f / (float)(BH * TDIM));
}

// -------- helpers -------------------------------------------------
__device__ __forceinline__ void cp16(void* s, const void* g) {
    unsigned sa = (unsigned)__cvta_generic_to_shared(s);
    asm volatile("cp.async.cg.shared.global [%0], [%1], 16;" :: "r"(sa), "l"(g));
}
#define CP_COMMIT() asm volatile("cp.async.commit_group;")
#define CP_WAIT0()  asm volatile("cp.async.wait_group 0;")

__device__ __forceinline__ void mma_f16(float* c, const unsigned* a, const unsigned* b) {
    asm("mma.sync.aligned.m16n8k16.row.col.f32.f16.f16.f32 "
        "{%0,%1,%2,%3}, {%4,%5,%6,%7}, {%8,%9}, {%0,%1,%2,%3};"
        : "+f"(c[0]), "+f"(c[1]), "+f"(c[2]), "+f"(c[3])
        : "r"(a[0]), "r"(a[1]), "r"(a[2]), "r"(a[3]), "r"(b[0]), "r"(b[1]));
}

__device__ __forceinline__ void ldm_x4(unsigned* r, uint32_t addr) {
    asm volatile("ldmatrix.sync.aligned.m8n8.x4.shared.b16 {%0,%1,%2,%3}, [%4];"
        : "=r"(r[0]), "=r"(r[1]), "=r"(r[2]), "=r"(r[3]) : "r"(addr));
}

__device__ __forceinline__ unsigned pack_h2(float a, float b) {
    __half2 h = __floats2half2_rn(a, b);
    return *(unsigned*)&h;
}

// -------- weight conversion fp32 -> fp16 (RN) ---------------------
__global__ void tohalf_kernel(const float* __restrict__ in,
                              __half* __restrict__ out, int n) {
    int i = (blockIdx.x * blockDim.x + threadIdx.x) * 4;
    if (i < n) {
        float4 v = *(const float4*)&in[i];
        *(__half2*)&out[i]     = __floats2half2_rn(v.x, v.y);
        *(__half2*)&out[i + 2] = __floats2half2_rn(v.z, v.w);
    }
}

// -------- LayerNorm: fp32 in, fp16 out ----------------------------
__global__ void ln_kernel(const float* __restrict__ x,
                          const float* __restrict__ w,
                          const float* __restrict__ b,
                          __half* __restrict__ out) {
    int row = blockIdx.x;
    int tid = threadIdx.x;
    int lane = tid & 31, warp = tid >> 5;
    const float* xr = x + (size_t)row * CDIM;
    __shared__ float rs[8], rq[8];

    float4 v = *(const float4*)&xr[tid * 4];
    float lsum = v.x + v.y + v.z + v.w;
    float lsq  = v.x * v.x + v.y * v.y + v.z * v.z + v.w * v.w;
#pragma unroll
    for (int o = 16; o > 0; o >>= 1) {
        lsum += __shfl_xor_sync(0xFFFFFFFFu, lsum, o);
        lsq  += __shfl_xor_sync(0xFFFFFFFFu, lsq, o);
    }
    if (lane == 0) { rs[warp] = lsum; rq[warp] = lsq; }
    __syncthreads();
    float tsum, tsq;
    {
        float a = rs[lane & 7], c = rq[lane & 7];
#pragma unroll
        for (int o = 4; o > 0; o >>= 1) {
            a += __shfl_xor_sync(0xFFFFFFFFu, a, o);
            c += __shfl_xor_sync(0xFFFFFFFFu, c, o);
        }
        tsum = a; tsq = c;
    }
    float mean = tsum * (1.0f / CDIM);
    float var = tsq * (1.0f / CDIM) - mean * mean;
    float rstd = rsqrtf(var + 1e-5f);

    float4 wv = *(const float4*)&w[tid * 4];
    float4 bv = *(const float4*)&b[tid * 4];
    __half2* orow = (__half2*)(out + (size_t)row * CDIM);
    orow[tid * 2] = __floats2half2_rn((v.x - mean) * rstd * wv.x + bv.x,
                                      (v.y - mean) * rstd * wv.y + bv.y);
    orow[tid * 2 + 1] = __floats2half2_rn((v.z - mean) * rstd * wv.z + bv.z,
                                          (v.w - mean) * rstd * wv.w + bv.w);
}

__device__ __forceinline__ float gelu_tanh(float x) {
    const float k0 = 0.7978845608028654f;
    const float k1 = 0.044715f;
    float u = k0 * (x + k1 * x * x * x);
    float t = __expf(2.0f * u);
    float th = (t - 1.0f) / (t + 1.0f);
    return 0.5f * x * (1.0f + th);
}

// -------- fp16 tensor-core GEMM: C = A[M,K]*W[N,K]^T + bias -------
// 128x128x32 tile, 256 threads, warp grid 2(m)x4(n), warp tile 64x32.
// Fragments via ldmatrix.x4 (A and B).
#define HST 40                  // smem row stride in halfs (80B)
#define HBUF (128 * HST)

__global__ __launch_bounds__(256, 2)
void gemm_f16(const __half* __restrict__ A, const __half* __restrict__ W,
              const float* __restrict__ bias, const float* __restrict__ resid,
              void* __restrict__ Cv, int M, int N, int K,
              int act, int outHalf) {
    extern __shared__ __half hsm[];
    __half* As = hsm;                   // [3][128][40]
    __half* Ws = hsm + 3 * HBUF;        // [3][128][40]

    int tid = threadIdx.x;
    int warp = tid >> 5, lane = tid & 31;
    int wm = warp >> 2, wn = warp & 3;
    int g = lane >> 2, tig = lane & 3;
    int rowBase = blockIdx.y * 128, colBase = blockIdx.x * 128;
    const __half* Ap = A + (size_t)rowBase * K;
    const __half* Wp = W + (size_t)colBase * K;

    uint32_t as_u32 = (uint32_t)__cvta_generic_to_shared(As);
    uint32_t ws_u32 = (uint32_t)__cvta_generic_to_shared(Ws);
    // ldmatrix per-lane offsets (in halfs)
    uint32_t a_lm = (uint32_t)((wm * 64 + (lane & 15)) * HST + (lane >> 4) * 8);
    uint32_t b_lm = (uint32_t)((wn * 32 + (lane & 7) + ((lane >> 4) << 3)) * HST
                               + ((lane >> 3) & 1) * 8);

    float acc[4][4][4];
#pragma unroll
    for (int i = 0; i < 4; i++)
#pragma unroll
        for (int j = 0; j < 4; j++)
#pragma unroll
            for (int p = 0; p < 4; p++) acc[i][j][p] = 0.f;

    // prologue: stage tiles 0 and 1
#pragma unroll
    for (int pt = 0; pt < 2; pt++) {
        int kt = pt * 32;
#pragma unroll
        for (int i = 0; i < 2; i++) {
            int idx = tid + i * 256;
            int r = idx >> 2, c4 = idx & 3;
            cp16(&As[pt * HBUF + r * HST + c4 * 8], Ap + (size_t)r * K + kt + c4 * 8);
            cp16(&Ws[pt * HBUF + r * HST + c4 * 8], Wp + (size_t)r * K + kt + c4 * 8);
        }
        CP_COMMIT();
    }

    int nt = K >> 5;
    int buf = 0;
    for (int t = 0; t < nt; t++) {
        if (t == nt - 1) asm volatile("cp.async.wait_group 0;" ::: "memory");
        else             asm volatile("cp.async.wait_group 1;" ::: "memory");
        __syncthreads();
        if (t + 2 < nt) {
            int kt = (t + 2) * 32;
            int nb = buf >= 1 ? buf - 1 : buf + 2;   // (t+2)%3
#pragma unroll
            for (int i = 0; i < 2; i++) {
                int idx = tid + i * 256;
                int r = idx >> 2, c4 = idx & 3;
                cp16(&As[nb * HBUF + r * HST + c4 * 8], Ap + (size_t)r * K + kt + c4 * 8);
                cp16(&Ws[nb * HBUF + r * HST + c4 * 8], Wp + (size_t)r * K + kt + c4 * 8);
            }
            CP_COMMIT();
        }
        uint32_t aaddr = as_u32 + (uint32_t)(buf * HBUF + a_lm) * 2;
        uint32_t baddr = ws_u32 + (uint32_t)(buf * HBUF + b_lm) * 2;
#pragma unroll
        for (int ks = 0; ks < 2; ks++) {
            int k0 = ks * 16;
            unsigned af[4][4], bf[4][2];
#pragma unroll
            for (int mi = 0; mi < 4; mi++)
                ldm_x4(af[mi], aaddr + (uint32_t)((mi * 16 * HST + k0) * 2));
#pragma unroll
            for (int njp = 0; njp < 2; njp++) {
                unsigned tmp[4];
                ldm_x4(tmp, baddr + (uint32_t)((njp * 16 * HST + k0) * 2));
                bf[2 * njp][0] = tmp[0];     bf[2 * njp][1] = tmp[1];
                bf[2 * njp + 1][0] = tmp[2]; bf[2 * njp + 1][1] = tmp[3];
            }
#pragma unroll
            for (int mi = 0; mi < 4; mi++)
#pragma unroll
                for (int nj = 0; nj < 4; nj++)
                    mma_f16(acc[mi][nj], af[mi], bf[nj]);
        }
        buf = buf < 2 ? buf + 1 : 0;
    }

    // epilogue
    float* Cf = (float*)Cv;
    __half* Ch = (__half*)Cv;
#pragma unroll
    for (int mi = 0; mi < 4; mi++) {
#pragma unroll
        for (int h2 = 0; h2 < 2; h2++) {
            int r = rowBase + wm * 64 + mi * 16 + g + h2 * 8;
            const float* rrow = resid ? resid + (size_t)r * N : nullptr;
#pragma unroll
            for (int nj = 0; nj < 4; nj++) {
                int c = colBase + wn * 32 + nj * 8 + 2 * tig;
                float v0 = acc[mi][nj][h2 * 2]     + bias[c];
                float v1 = acc[mi][nj][h2 * 2 + 1] + bias[c + 1];
                if (act == 1) { v0 = gelu_tanh(v0); v1 = gelu_tanh(v1); }
                if (rrow) { v0 += rrow[c]; v1 += rrow[c + 1]; }
                if (outHalf) {
                    *(__half2*)&Ch[(size_t)r * N + c] = __floats2half2_rn(v0, v1);
                } else {
                    *(float2*)&Cf[(size_t)r * N + c] = make_float2(v0, v1);
                }
            }
        }
    }
}

// -------- fp16 flash attention: 128q x 64k tiles -------------------
// P in registers; K/Q fragments via ldmatrix.x4; V via ldmatrix.trans.
#define AST 72                  // halfs stride (144B)
#define KVN (64 * AST)

__global__ __launch_bounds__(256, 2)
void flash_attn_f16(const __half* __restrict__ qkv, __half* __restrict__ y) {
    extern __shared__ __half hs[];
    __half* Qs = hs;                     // [128][72]
    __half* Ks = Qs + 128 * AST;         // [2][64][72]
    __half* Vs = Ks + 2 * KVN;           // [2][64][72]
    float* hrow = (float*)(Vs + 2 * KVN);// [128]

    int tid = threadIdx.x;
    int warp = tid >> 5, lane = tid & 31;
    int g = lane >> 2, tig = lane & 3;
    int qt = (TDIM / 128 - 1) - blockIdx.x;   // long tiles first
    int bh = blockIdx.y;
    int b = bh >> 4, h = bh & 15;
    int qb = qt * 128;
    const __half* base = qkv + (size_t)b * TDIM * QKVC + h * HD;

    // prefetch Q (128x64) + K0 + V0
#pragma unroll
    for (int i = 0; i < 4; i++) {
        int idx = tid + i * 256;
        int r = idx >> 3, c = (idx & 7) * 8;
        cp16(&Qs[r * AST + c], &base[(size_t)(qb + r) * QKVC + c]);
    }
#pragma unroll
    for (int i = 0; i < 2; i++) {
        int idx = tid + i * 256;
        int r = idx >> 3, c = (idx & 7) * 8;
        cp16(&Ks[r * AST + c], &base[(size_t)r * QKVC + CDIM + c]);
        cp16(&Vs[r * AST + c], &base[(size_t)r * QKVC + 2 * CDIM + c]);
    }
    CP_COMMIT();
    CP_WAIT0();
    __syncthreads();

    uint32_t qs_u32 = (uint32_t)__cvta_generic_to_shared(Qs);
    uint32_t ks_u32 = (uint32_t)__cvta_generic_to_shared(Ks);
    uint32_t vs_u32 = (uint32_t)__cvta_generic_to_shared(Vs);
    uint32_t q_lm = (uint32_t)((warp * 16 + (lane & 15)) * AST + (lane >> 4) * 8);
    uint32_t k_lm = (uint32_t)(((lane & 7) + ((lane >> 4) << 3)) * AST
                               + ((lane >> 3) & 1) * 8);
    uint32_t v_lm = (uint32_t)(((lane & 15) * AST + (lane >> 4) * 8) * 2);

    // hoist Q fragments: 4 k16-steps via ldmatrix
    unsigned qf[4][4];
#pragma unroll
    for (int ks = 0; ks < 4; ks++)
        ldm_x4(qf[ks], qs_u32 + (q_lm + ks * 16) * 2);

    float m0 = NEG_BIG, m1 = NEG_BIG, l0 = 0.f, l1 = 0.f, w0 = 0.f, w1 = 0.f;
    float oacc[8][4];
#pragma unroll
    for (int nj = 0; nj < 8; nj++)
#pragma unroll
        for (int p = 0; p < 4; p++) oacc[nj][p] = 0.f;

    int row0 = qb + warp * 16 + g, row1 = row0 + 8;
    int ni = 2 * qt + 2;

    for (int i = 0; i < ni; i++) {
        CP_WAIT0();
        __syncthreads();
        if (i + 1 < ni) {
            int nb = (i + 1) & 1, kb2 = (i + 1) * 64;
#pragma unroll
            for (int it = 0; it < 2; it++) {
                int idx = tid + it * 256;
                int r = idx >> 3, c = (idx & 7) * 8;
                cp16(&Ks[nb * KVN + r * AST + c],
                     &base[(size_t)(kb2 + r) * QKVC + CDIM + c]);
                cp16(&Vs[nb * KVN + r * AST + c],
                     &base[(size_t)(kb2 + r) * QKVC + 2 * CDIM + c]);
            }
            CP_COMMIT();
        }
        int kb = i * 64;
        if (qb + warp * 16 + 15 >= kb) {   // warp has unmasked rows here
            uint32_t kaddr = ks_u32 + (uint32_t)((i & 1) * KVN + k_lm) * 2;

            // ---- S = Q K^T ----
            float sacc[8][4];
#pragma unroll
            for (int nj = 0; nj < 8; nj++)
#pragma unroll
                for (int p = 0; p < 4; p++) sacc[nj][p] = 0.f;
#pragma unroll
            for (int ks = 0; ks < 4; ks++) {
#pragma unroll
                for (int njp = 0; njp < 4; njp++) {
                    unsigned tmp[4];
                    ldm_x4(tmp, kaddr + (uint32_t)((njp * 16 * AST + ks * 16) * 2));
                    unsigned bfa[2] = {tmp[0], tmp[1]};
                    unsigned bfb[2] = {tmp[2], tmp[3]};
                    mma_f16(sacc[2 * njp], qf[ks], bfa);
                    mma_f16(sacc[2 * njp + 1], qf[ks], bfb);
                }
            }

            // ---- scale + mask + row max ----
            float mx0 = NEG_BIG, mx1 = NEG_BIG;
#pragma unroll
            for (int nj = 0; nj < 8; nj++) {
                int cg = kb + nj * 8 + 2 * tig;
                float s0 = sacc[nj][0] * 0.125f;
                float s1 = sacc[nj][1] * 0.125f;
                float s2 = sacc[nj][2] * 0.125f;
                float s3 = sacc[nj][3] * 0.125f;
                if (cg > row0) s0 = NEG_BIG;
                if (cg + 1 > row0) s1 = NEG_BIG;
                if (cg > row1) s2 = NEG_BIG;
                if (cg + 1 > row1) s3 = NEG_BIG;
                sacc[nj][0] = s0; sacc[nj][1] = s1;
                sacc[nj][2] = s2; sacc[nj][3] = s3;
                mx0 = fmaxf(mx0, fmaxf(s0, s1));
                mx1 = fmaxf(mx1, fmaxf(s2, s3));
            }
            mx0 = fmaxf(mx0, __shfl_xor_sync(0xFFFFFFFFu, mx0, 1));
            mx0 = fmaxf(mx0, __shfl_xor_sync(0xFFFFFFFFu, mx0, 2));
            mx1 = fmaxf(mx1, __shfl_xor_sync(0xFFFFFFFFu, mx1, 1));
            mx1 = fmaxf(mx1, __shfl_xor_sync(0xFFFFFFFFu, mx1, 2));
            float mn0 = fmaxf(m0, mx0), mn1 = fmaxf(m1, mx1);

            // ---- exp + sums; P packed to fp16 A-fragments ----
            unsigned pe[8][2];
            float se0 = 0.f, se1 = 0.f, sw0 = 0.f, sw1 = 0.f;
#pragma unroll
            for (int nj = 0; nj < 8; nj++) {
                float s0 = sacc[nj][0], s1 = sacc[nj][1];
                float s2 = sacc[nj][2], s3 = sacc[nj][3];
                float e0 = __expf(s0 - mn0), e1 = __expf(s1 - mn0);
                float e2 = __expf(s2 - mn1), e3 = __expf(s3 - mn1);
                se0 += e0 + e1; sw0 += e0 * s0 + e1 * s1;
                se1 += e2 + e3; sw1 += e2 * s2 + e3 * s3;
                pe[nj][0] = pack_h2(e0, e1);
                pe[nj][1] = pack_h2(e2, e3);
            }
            se0 += __shfl_xor_sync(0xFFFFFFFFu, se0, 1);
            se0 += __shfl_xor_sync(0xFFFFFFFFu, se0, 2);
            sw0 += __shfl_xor_sync(0xFFFFFFFFu, sw0, 1);
            sw0 += __shfl_xor_sync(0xFFFFFFFFu, sw0, 2);
            se1 += __shfl_xor_sync(0xFFFFFFFFu, se1, 1);
            se1 += __shfl_xor_sync(0xFFFFFFFFu, se1, 2);
            sw1 += __shfl_xor_sync(0xFFFFFFFFu, sw1, 1);
            sw1 += __shfl_xor_sync(0xFFFFFFFFu, sw1, 2);

            float c0f = __expf(m0 - mn0), c1f = __expf(m1 - mn1);
            l0 = l0 * c0f + se0; w0 = w0 * c0f + sw0; m0 = mn0;
            l1 = l1 * c1f + se1; w1 = w1 * c1f + sw1; m1 = mn1;
#pragma unroll
            for (int nj = 0; nj < 8; nj++) {
                oacc[nj][0] *= c0f; oacc[nj][1] *= c0f;
                oacc[nj][2] *= c1f; oacc[nj][3] *= c1f;
            }

            // ---- O += P V : V fragments via ldmatrix.x4.trans ----
            uint32_t vbase = vs_u32 + (uint32_t)((i & 1) * KVN * 2) + v_lm;
#pragma unroll
            for (int ks = 0; ks < 4; ks++) {
                unsigned af[4] = { pe[2 * ks][0], pe[2 * ks][1],
                                   pe[2 * ks + 1][0], pe[2 * ks + 1][1] };
#pragma unroll
                for (int dj = 0; dj < 4; dj++) {
                    uint32_t addr = vbase + (uint32_t)((ks * 16 * AST + dj * 16) * 2);
                    unsigned v0, v1, v2, v3;
                    asm volatile(
                        "ldmatrix.sync.aligned.m8n8.x4.trans.shared.b16 "
                        "{%0,%1,%2,%3}, [%4];"
                        : "=r"(v0), "=r"(v1), "=r"(v2), "=r"(v3) : "r"(addr));
                    unsigned bfa[2] = {v0, v1};
                    unsigned bfb[2] = {v2, v3};
                    mma_f16(oacc[2 * dj], af, bfa);
                    mma_f16(oacc[2 * dj + 1], af, bfb);
                }
            }
        }
    }

    // write O (divide by l) as fp16 (attnproj A operand)
    {
        float li0 = 1.0f / l0, li1 = 1.0f / l1;
#pragma unroll
        for (int nj = 0; nj < 8; nj++) {
            int c = h * HD + nj * 8 + 2 * tig;
            *(__half2*)&y[(size_t)(b * TDIM + row0) * CDIM + c] =
                __floats2half2_rn(oacc[nj][0] * li0, oacc[nj][1] * li0);
            *(__half2*)&y[(size_t)(b * TDIM + row1) * CDIM + c] =
                __floats2half2_rn(oacc[nj][2] * li1, oacc[nj][3] * li1);
        }
    }

    // entropy: H_row = m + log(S) - W/S
    if (tig == 0) {
        hrow[warp * 16 + g]     = m0 + logf(l0) - w0 / l0;
        hrow[warp * 16 + g + 8] = m1 + logf(l1) - w1 / l1;
    }
    __syncthreads();
    if (tid == 0) {
        float tot = 0.f;
        for (int i = 0; i < 128; i++) tot += hrow[i];
        atomicAdd(&g_ent, tot);
    }
}

// ------------------------------------------------------------------
extern "C" void kernel_launch(void* const* d_in, const int* in_sizes, int n_in,
                              void* d_out, int out_size) {
    const float* x          = (const float*)d_in[0];
    const float* ln1_w      = (const float*)d_in[1];
    const float* ln1_b      = (const float*)d_in[2];
    const float* attn_w     = (const float*)d_in[3];
    const float* attn_b     = (const float*)d_in[4];
    const float* attnproj_w = (const float*)d_in[5];
    const float* attnproj_b = (const float*)d_in[6];
    const float* ln2_w      = (const float*)d_in[7];
    const float* ln2_b      = (const float*)d_in[8];
    const float* fc_w       = (const float*)d_in[9];
    const float* fc_b       = (const float*)d_in[10];
    const float* proj_w     = (const float*)d_in[11];
    const float* proj_b     = (const float*)d_in[12];
    float* out = (float*)d_out;

    __half *p_h, *p_qkv, *p_y, *p_m, *p_wh;
    float *p_x1;
    cudaGetSymbolAddress((void**)&p_h,   g_h);
    cudaGetSymbolAddress((void**)&p_qkv, g_qkv);
    cudaGetSymbolAddress((void**)&p_y,   g_y);
    cudaGetSymbolAddress((void**)&p_x1,  g_x1);
    cudaGetSymbolAddress((void**)&p_m,   g_m);
    cudaGetSymbolAddress((void**)&p_wh,  g_wh);

    static int gemm_smem = 6 * HBUF * 2;                          // 61440 B
    static int attn_smem = (128 * AST + 4 * KVN) * 2 + 128 * 4;   // ~56 KB
    cudaFuncSetAttribute(gemm_f16,
                         cudaFuncAttributeMaxDynamicSharedMemorySize, gemm_smem);
    cudaFuncSetAttribute(flash_attn_f16,
                         cudaFuncAttributeMaxDynamicSharedMemorySize, attn_smem);

    zero_ent_kernel<<<1, 1>>>();

    // RN-convert weights to fp16 once per launch
    tohalf_kernel<<<3145728 / 1024, 256>>>(attn_w,     p_wh + WR_ATTN,  3145728);
    tohalf_kernel<<<1048576 / 1024, 256>>>(attnproj_w, p_wh + WR_APROJ, 1048576);
    tohalf_kernel<<<4194304 / 1024, 256>>>(fc_w,       p_wh + WR_FC,    4194304);
    tohalf_kernel<<<4194304 / 1024, 256>>>(proj_w,     p_wh + WR_PROJ,  4194304);

    // h = LN1(x)  (fp16 out)
    ln_kernel<<<BT, 256>>>(x, ln1_w, ln1_b, p_h);

    // qkv = h @ attn_w^T + attn_b   (fp16 out -> attention operands)
    gemm_f16<<<dim3(QKVC / 128, BT / 128), 256, gemm_smem>>>(
        p_h, p_wh + WR_ATTN, attn_b, nullptr, p_qkv, BT, QKVC, CDIM, 0, 1);

    // attention (+entropy) -> y fp16
    flash_attn_f16<<<dim3(TDIM / 128, BH), 256, attn_smem>>>(p_qkv, p_y);

    // x1 = x + y @ attnproj_w^T + attnproj_b   (fp32 out)
    gemm_f16<<<dim3(CDIM / 128, BT / 128), 256, gemm_smem>>>(
        p_y, p_wh + WR_APROJ, attnproj_b, x, p_x1, BT, CDIM, CDIM, 0, 0);

    // h = LN2(x1)  (fp16 out)
    ln_kernel<<<BT, 256>>>(p_x1, ln2_w, ln2_b, p_h);

    // m = gelu(h @ fc_w^T + fc_b)   (fp16 out)
    gemm_f16<<<dim3(FFC / 128, BT / 128), 256, gemm_smem>>>(
        p_h, p_wh + WR_FC, fc_b, nullptr, p_m, BT, FFC, CDIM, 1, 1);

    // out = x1 + m @ proj_w^T + proj_b   (fp32 out)
    gemm_f16<<<dim3(CDIM / 128, BT / 128), 256, gemm_smem>>>(
        p_m, p_wh + WR_PROJ, proj_b, p_x1, out, BT, CDIM, FFC, 0, 0);

    // entropy scalar
    finalize_kernel<<<1, 1>>>(out, out_size);
}

// round 15
// speedup vs baseline: 2.0184x; 1.0621x over previous
#include <cuda_runtime.h>
#include <cuda_fp16.h>
#include <math.h>
#include <stdint.h>

// Problem constants
#define BATCH 2
#define TDIM 2048
#define CDIM 1024
#define HN 16
#define HD 64
#define BT (BATCH * TDIM)        // 4096 rows
#define BH (BATCH * HN)          // 32 batch-heads
#define QKVC (3 * CDIM)          // 3072
#define FFC (4 * CDIM)           // 4096

#define NEG_BIG (-1e30f)

// -------- scratch (static device globals; no allocation) ----------
__device__ __half g_h[BT * CDIM];      // LN output (GEMM A operand)
__device__ __half g_qkv[BT * QKVC];    // qkv fp16 (attention operand)
__device__ __half g_y[BT * CDIM];      // attention out (attnproj A operand)
__device__ float  g_x1[BT * CDIM];     // x + attn (fp32 residual)
__device__ __half g_m[BT * FFC];       // gelu(fc) (proj A operand)
__device__ __half g_wh[12582912];      // fp16 weights: attn|attnproj|fc|proj
__device__ float  g_ent;

#define WR_ATTN  0
#define WR_APROJ 3145728
#define WR_FC    4194304
#define WR_PROJ  8388608

// ------------------------------------------------------------------
__global__ void finalize_kernel(float* out, int out_size) {
    if (out_size > BT * CDIM)
        out[BT * CDIM] = g_ent * (1.0f / (float)(BH * TDIM));
}

// -------- helpers -------------------------------------------------
__device__ __forceinline__ void cp16(void* s, const void* g) {
    unsigned sa = (unsigned)__cvta_generic_to_shared(s);
    asm volatile("cp.async.cg.shared.global [%0], [%1], 16;" :: "r"(sa), "l"(g));
}
#define CP_COMMIT() asm volatile("cp.async.commit_group;")
#define CP_WAIT0()  asm volatile("cp.async.wait_group 0;")

__device__ __forceinline__ void mma_f16(float* c, const unsigned* a, const unsigned* b) {
    asm("mma.sync.aligned.m16n8k16.row.col.f32.f16.f16.f32 "
        "{%0,%1,%2,%3}, {%4,%5,%6,%7}, {%8,%9}, {%0,%1,%2,%3};"
        : "+f"(c[0]), "+f"(c[1]), "+f"(c[2]), "+f"(c[3])
        : "r"(a[0]), "r"(a[1]), "r"(a[2]), "r"(a[3]), "r"(b[0]), "r"(b[1]));
}

__device__ __forceinline__ void ldm_x4(unsigned* r, uint32_t addr) {
    asm volatile("ldmatrix.sync.aligned.m8n8.x4.shared.b16 {%0,%1,%2,%3}, [%4];"
        : "=r"(r[0]), "=r"(r[1]), "=r"(r[2]), "=r"(r[3]) : "r"(addr));
}

__device__ __forceinline__ unsigned pack_h2(float a, float b) {
    __half2 h = __floats2half2_rn(a, b);
    return *(unsigned*)&h;
}

// -------- weight conversion fp32 -> fp16 (RN) ---------------------
__global__ void tohalf_kernel(const float* __restrict__ in,
                              __half* __restrict__ out, int n) {
    int i = (blockIdx.x * blockDim.x + threadIdx.x) * 4;
    if (i < n) {
        float4 v = *(const float4*)&in[i];
        *(__half2*)&out[i]     = __floats2half2_rn(v.x, v.y);
        *(__half2*)&out[i + 2] = __floats2half2_rn(v.z, v.w);
    }
}

// -------- LayerNorm: fp32 in, fp16 out (optionally zeroes g_ent) --
__global__ void ln_kernel(const float* __restrict__ x,
                          const float* __restrict__ w,
                          const float* __restrict__ b,
                          __half* __restrict__ out, int zent) {
    int row = blockIdx.x;
    int tid = threadIdx.x;
    int lane = tid & 31, warp = tid >> 5;
    if (zent && row == 0 && tid == 0) g_ent = 0.0f;
    const float* xr = x + (size_t)row * CDIM;
    __shared__ float rs[8], rq[8];

    float4 v = *(const float4*)&xr[tid * 4];
    float lsum = v.x + v.y + v.z + v.w;
    float lsq  = v.x * v.x + v.y * v.y + v.z * v.z + v.w * v.w;
#pragma unroll
    for (int o = 16; o > 0; o >>= 1) {
        lsum += __shfl_xor_sync(0xFFFFFFFFu, lsum, o);
        lsq  += __shfl_xor_sync(0xFFFFFFFFu, lsq, o);
    }
    if (lane == 0) { rs[warp] = lsum; rq[warp] = lsq; }
    __syncthreads();
    float tsum, tsq;
    {
        float a = rs[lane & 7], c = rq[lane & 7];
#pragma unroll
        for (int o = 4; o > 0; o >>= 1) {
            a += __shfl_xor_sync(0xFFFFFFFFu, a, o);
            c += __shfl_xor_sync(0xFFFFFFFFu, c, o);
        }
        tsum = a; tsq = c;
    }
    float mean = tsum * (1.0f / CDIM);
    float var = tsq * (1.0f / CDIM) - mean * mean;
    float rstd = rsqrtf(var + 1e-5f);

    float4 wv = *(const float4*)&w[tid * 4];
    float4 bv = *(const float4*)&b[tid * 4];
    __half2* orow = (__half2*)(out + (size_t)row * CDIM);
    orow[tid * 2] = __floats2half2_rn((v.x - mean) * rstd * wv.x + bv.x,
                                      (v.y - mean) * rstd * wv.y + bv.y);
    orow[tid * 2 + 1] = __floats2half2_rn((v.z - mean) * rstd * wv.z + bv.z,
                                          (v.w - mean) * rstd * wv.w + bv.w);
}

__device__ __forceinline__ float gelu_tanh(float x) {
    const float k0 = 0.7978845608028654f;
    const float k1 = 0.044715f;
    float u = k0 * (x + k1 * x * x * x);
    float t = __expf(2.0f * u);
    float th = (t - 1.0f) / (t + 1.0f);
    return 0.5f * x * (1.0f + th);
}

// -------- fp16 tensor-core GEMM: C = A[M,K]*W[N,K]^T + bias -------
// 128x128x64 tile (k-tile 64 halves loop overhead), 256 threads,
// warp grid 2(m)x4(n), warp tile 64x32. ldmatrix fragments.
#define HST 72                  // smem row stride in halfs (144B)
#define HBUF (128 * HST)        // halfs per matrix stage

__global__ __launch_bounds__(256, 2)
void gemm_f16(const __half* __restrict__ A, const __half* __restrict__ W,
              const float* __restrict__ bias, const float* __restrict__ resid,
              void* __restrict__ Cv, int M, int N, int K,
              int act, int outHalf) {
    extern __shared__ __half hsm[];
    __half* As = hsm;                   // [3][128][72]
    __half* Ws = hsm + 3 * HBUF;        // [3][128][72]

    int tid = threadIdx.x;
    int warp = tid >> 5, lane = tid & 31;
    int wm = warp >> 2, wn = warp & 3;
    int g = lane >> 2, tig = lane & 3;
    int rowBase = blockIdx.y * 128, colBase = blockIdx.x * 128;
    const __half* Ap = A + (size_t)rowBase * K;
    const __half* Wp = W + (size_t)colBase * K;

    uint32_t as_u32 = (uint32_t)__cvta_generic_to_shared(As);
    uint32_t ws_u32 = (uint32_t)__cvta_generic_to_shared(Ws);
    uint32_t a_lm = (uint32_t)((wm * 64 + (lane & 15)) * HST + (lane >> 4) * 8);
    uint32_t b_lm = (uint32_t)((wn * 32 + (lane & 7) + ((lane >> 4) << 3)) * HST
                               + ((lane >> 3) & 1) * 8);

    float acc[4][4][4];
#pragma unroll
    for (int i = 0; i < 4; i++)
#pragma unroll
        for (int j = 0; j < 4; j++)
#pragma unroll
            for (int p = 0; p < 4; p++) acc[i][j][p] = 0.f;

    // prologue: stage tiles 0 and 1 (k-tile = 64 cols = 8 chunks of 8)
#pragma unroll
    for (int pt = 0; pt < 2; pt++) {
        int kt = pt * 64;
#pragma unroll
        for (int i = 0; i < 4; i++) {
            int idx = tid + i * 256;            // 0..1023
            int r = idx >> 3, c = (idx & 7) * 8;
            cp16(&As[pt * HBUF + r * HST + c], Ap + (size_t)r * K + kt + c);
            cp16(&Ws[pt * HBUF + r * HST + c], Wp + (size_t)r * K + kt + c);
        }
        CP_COMMIT();
    }

    int nt = K >> 6;
    int buf = 0;
    for (int t = 0; t < nt; t++) {
        if (t == nt - 1) asm volatile("cp.async.wait_group 0;" ::: "memory");
        else             asm volatile("cp.async.wait_group 1;" ::: "memory");
        __syncthreads();
        if (t + 2 < nt) {
            int kt = (t + 2) * 64;
            int nb = buf >= 1 ? buf - 1 : buf + 2;   // (t+2)%3
#pragma unroll
            for (int i = 0; i < 4; i++) {
                int idx = tid + i * 256;
                int r = idx >> 3, c = (idx & 7) * 8;
                cp16(&As[nb * HBUF + r * HST + c], Ap + (size_t)r * K + kt + c);
                cp16(&Ws[nb * HBUF + r * HST + c], Wp + (size_t)r * K + kt + c);
            }
            CP_COMMIT();
        }
        uint32_t aaddr = as_u32 + (uint32_t)(buf * HBUF + a_lm) * 2;
        uint32_t baddr = ws_u32 + (uint32_t)(buf * HBUF + b_lm) * 2;
#pragma unroll
        for (int ks = 0; ks < 4; ks++) {
            int k0 = ks * 16;
            unsigned af[4][4], bf[4][2];
#pragma unroll
            for (int mi = 0; mi < 4; mi++)
                ldm_x4(af[mi], aaddr + (uint32_t)((mi * 16 * HST + k0) * 2));
#pragma unroll
            for (int njp = 0; njp < 2; njp++) {
                unsigned tmp[4];
                ldm_x4(tmp, baddr + (uint32_t)((njp * 16 * HST + k0) * 2));
                bf[2 * njp][0] = tmp[0];     bf[2 * njp][1] = tmp[1];
                bf[2 * njp + 1][0] = tmp[2]; bf[2 * njp + 1][1] = tmp[3];
            }
#pragma unroll
            for (int mi = 0; mi < 4; mi++)
#pragma unroll
                for (int nj = 0; nj < 4; nj++)
                    mma_f16(acc[mi][nj], af[mi], bf[nj]);
        }
        buf = buf < 2 ? buf + 1 : 0;
    }

    // epilogue
    float* Cf = (float*)Cv;
    __half* Ch = (__half*)Cv;
#pragma unroll
    for (int mi = 0; mi < 4; mi++) {
#pragma unroll
        for (int h2 = 0; h2 < 2; h2++) {
            int r = rowBase + wm * 64 + mi * 16 + g + h2 * 8;
            const float* rrow = resid ? resid + (size_t)r * N : nullptr;
#pragma unroll
            for (int nj = 0; nj < 4; nj++) {
                int c = colBase + wn * 32 + nj * 8 + 2 * tig;
                float v0 = acc[mi][nj][h2 * 2]     + bias[c];
                float v1 = acc[mi][nj][h2 * 2 + 1] + bias[c + 1];
                if (act == 1) { v0 = gelu_tanh(v0); v1 = gelu_tanh(v1); }
                if (rrow) { v0 += rrow[c]; v1 += rrow[c + 1]; }
                if (outHalf) {
                    *(__half2*)&Ch[(size_t)r * N + c] = __floats2half2_rn(v0, v1);
                } else {
                    *(float2*)&Cf[(size_t)r * N + c] = make_float2(v0, v1);
                }
            }
        }
    }
}

// -------- fp16 flash attention: 128q x 64k tiles -------------------
// P in registers; K/Q fragments via ldmatrix.x4; V via ldmatrix.trans.
#define AST 72                  // halfs stride (144B)
#define KVN (64 * AST)

__global__ __launch_bounds__(256, 2)
void flash_attn_f16(const __half* __restrict__ qkv, __half* __restrict__ y) {
    extern __shared__ __half hs[];
    __half* Qs = hs;                     // [128][72]
    __half* Ks = Qs + 128 * AST;         // [2][64][72]
    __half* Vs = Ks + 2 * KVN;           // [2][64][72]
    float* hrow = (float*)(Vs + 2 * KVN);// [128]

    int tid = threadIdx.x;
    int warp = tid >> 5, lane = tid & 31;
    int g = lane >> 2, tig = lane & 3;
    int qt = (TDIM / 128 - 1) - blockIdx.x;   // long tiles first
    int bh = blockIdx.y;
    int b = bh >> 4, h = bh & 15;
    int qb = qt * 128;
    const __half* base = qkv + (size_t)b * TDIM * QKVC + h * HD;

    // prefetch Q (128x64) + K0 + V0
#pragma unroll
    for (int i = 0; i < 4; i++) {
        int idx = tid + i * 256;
        int r = idx >> 3, c = (idx & 7) * 8;
        cp16(&Qs[r * AST + c], &base[(size_t)(qb + r) * QKVC + c]);
    }
#pragma unroll
    for (int i = 0; i < 2; i++) {
        int idx = tid + i * 256;
        int r = idx >> 3, c = (idx & 7) * 8;
        cp16(&Ks[r * AST + c], &base[(size_t)r * QKVC + CDIM + c]);
        cp16(&Vs[r * AST + c], &base[(size_t)r * QKVC + 2 * CDIM + c]);
    }
    CP_COMMIT();
    CP_WAIT0();
    __syncthreads();

    uint32_t qs_u32 = (uint32_t)__cvta_generic_to_shared(Qs);
    uint32_t ks_u32 = (uint32_t)__cvta_generic_to_shared(Ks);
    uint32_t vs_u32 = (uint32_t)__cvta_generic_to_shared(Vs);
    uint32_t q_lm = (uint32_t)((warp * 16 + (lane & 15)) * AST + (lane >> 4) * 8);
    uint32_t k_lm = (uint32_t)(((lane & 7) + ((lane >> 4) << 3)) * AST
                               + ((lane >> 3) & 1) * 8);
    uint32_t v_lm = (uint32_t)(((lane & 15) * AST + (lane >> 4) * 8) * 2);

    // hoist Q fragments: 4 k16-steps via ldmatrix
    unsigned qf[4][4];
#pragma unroll
    for (int ks = 0; ks < 4; ks++)
        ldm_x4(qf[ks], qs_u32 + (q_lm + ks * 16) * 2);

    float m0 = NEG_BIG, m1 = NEG_BIG, l0 = 0.f, l1 = 0.f, w0 = 0.f, w1 = 0.f;
    float oacc[8][4];
#pragma unroll
    for (int nj = 0; nj < 8; nj++)
#pragma unroll
        for (int p = 0; p < 4; p++) oacc[nj][p] = 0.f;

    int row0 = qb + warp * 16 + g, row1 = row0 + 8;
    int ni = 2 * qt + 2;

    for (int i = 0; i < ni; i++) {
        CP_WAIT0();
        __syncthreads();
        if (i + 1 < ni) {
            int nb = (i + 1) & 1, kb2 = (i + 1) * 64;
#pragma unroll
            for (int it = 0; it < 2; it++) {
                int idx = tid + it * 256;
                int r = idx >> 3, c = (idx & 7) * 8;
                cp16(&Ks[nb * KVN + r * AST + c],
                     &base[(size_t)(kb2 + r) * QKVC + CDIM + c]);
                cp16(&Vs[nb * KVN + r * AST + c],
                     &base[(size_t)(kb2 + r) * QKVC + 2 * CDIM + c]);
            }
            CP_COMMIT();
        }
        int kb = i * 64;
        if (qb + warp * 16 + 15 >= kb) {   // warp has unmasked rows here
            uint32_t kaddr = ks_u32 + (uint32_t)((i & 1) * KVN + k_lm) * 2;

            // ---- S = Q K^T ----
            float sacc[8][4];
#pragma unroll
            for (int nj = 0; nj < 8; nj++)
#pragma unroll
                for (int p = 0; p < 4; p++) sacc[nj][p] = 0.f;
#pragma unroll
            for (int ks = 0; ks < 4; ks++) {
#pragma unroll
                for (int njp = 0; njp < 4; njp++) {
                    unsigned tmp[4];
                    ldm_x4(tmp, kaddr + (uint32_t)((njp * 16 * AST + ks * 16) * 2));
                    unsigned bfa[2] = {tmp[0], tmp[1]};
                    unsigned bfb[2] = {tmp[2], tmp[3]};
                    mma_f16(sacc[2 * njp], qf[ks], bfa);
                    mma_f16(sacc[2 * njp + 1], qf[ks], bfb);
                }
            }

            // ---- scale + mask + row max ----
            float mx0 = NEG_BIG, mx1 = NEG_BIG;
#pragma unroll
            for (int nj = 0; nj < 8; nj++) {
                int cg = kb + nj * 8 + 2 * tig;
                float s0 = sacc[nj][0] * 0.125f;
                float s1 = sacc[nj][1] * 0.125f;
                float s2 = sacc[nj][2] * 0.125f;
                float s3 = sacc[nj][3] * 0.125f;
                if (cg > row0) s0 = NEG_BIG;
                if (cg + 1 > row0) s1 = NEG_BIG;
                if (cg > row1) s2 = NEG_BIG;
                if (cg + 1 > row1) s3 = NEG_BIG;
                sacc[nj][0] = s0; sacc[nj][1] = s1;
                sacc[nj][2] = s2; sacc[nj][3] = s3;
                mx0 = fmaxf(mx0, fmaxf(s0, s1));
                mx1 = fmaxf(mx1, fmaxf(s2, s3));
            }
            mx0 = fmaxf(mx0, __shfl_xor_sync(0xFFFFFFFFu, mx0, 1));
            mx0 = fmaxf(mx0, __shfl_xor_sync(0xFFFFFFFFu, mx0, 2));
            mx1 = fmaxf(mx1, __shfl_xor_sync(0xFFFFFFFFu, mx1, 1));
            mx1 = fmaxf(mx1, __shfl_xor_sync(0xFFFFFFFFu, mx1, 2));
            float mn0 = fmaxf(m0, mx0), mn1 = fmaxf(m1, mx1);

            // ---- exp + sums; P packed to fp16 A-fragments ----
            unsigned pe[8][2];
            float se0 = 0.f, se1 = 0.f, sw0 = 0.f, sw1 = 0.f;
#pragma unroll
            for (int nj = 0; nj < 8; nj++) {
                float s0 = sacc[nj][0], s1 = sacc[nj][1];
                float s2 = sacc[nj][2], s3 = sacc[nj][3];
                float e0 = __expf(s0 - mn0), e1 = __expf(s1 - mn0);
                float e2 = __expf(s2 - mn1), e3 = __expf(s3 - mn1);
                se0 += e0 + e1; sw0 += e0 * s0 + e1 * s1;
                se1 += e2 + e3; sw1 += e2 * s2 + e3 * s3;
                pe[nj][0] = pack_h2(e0, e1);
                pe[nj][1] = pack_h2(e2, e3);
            }
            se0 += __shfl_xor_sync(0xFFFFFFFFu, se0, 1);
            se0 += __shfl_xor_sync(0xFFFFFFFFu, se0, 2);
            sw0 += __shfl_xor_sync(0xFFFFFFFFu, sw0, 1);
            sw0 += __shfl_xor_sync(0xFFFFFFFFu, sw0, 2);
            se1 += __shfl_xor_sync(0xFFFFFFFFu, se1, 1);
            se1 += __shfl_xor_sync(0xFFFFFFFFu, se1, 2);
            sw1 += __shfl_xor_sync(0xFFFFFFFFu, sw1, 1);
            sw1 += __shfl_xor_sync(0xFFFFFFFFu, sw1, 2);

            float c0f = __expf(m0 - mn0), c1f = __expf(m1 - mn1);
            l0 = l0 * c0f + se0; w0 = w0 * c0f + sw0; m0 = mn0;
            l1 = l1 * c1f + se1; w1 = w1 * c1f + sw1; m1 = mn1;
#pragma unroll
            for (int nj = 0; nj < 8; nj++) {
                oacc[nj][0] *= c0f; oacc[nj][1] *= c0f;
                oacc[nj][2] *= c1f; oacc[nj][3] *= c1f;
            }

            // ---- O += P V : V fragments via ldmatrix.x4.trans ----
            uint32_t vbase = vs_u32 + (uint32_t)((i & 1) * KVN * 2) + v_lm;
#pragma unroll
            for (int ks = 0; ks < 4; ks++) {
                unsigned af[4] = { pe[2 * ks][0], pe[2 * ks][1],
                                   pe[2 * ks + 1][0], pe[2 * ks + 1][1] };
#pragma unroll
                for (int dj = 0; dj < 4; dj++) {
                    uint32_t addr = vbase + (uint32_t)((ks * 16 * AST + dj * 16) * 2);
                    unsigned v0, v1, v2, v3;
                    asm volatile(
                        "ldmatrix.sync.aligned.m8n8.x4.trans.shared.b16 "
                        "{%0,%1,%2,%3}, [%4];"
                        : "=r"(v0), "=r"(v1), "=r"(v2), "=r"(v3) : "r"(addr));
                    unsigned bfa[2] = {v0, v1};
                    unsigned bfb[2] = {v2, v3};
                    mma_f16(oacc[2 * dj], af, bfa);
                    mma_f16(oacc[2 * dj + 1], af, bfb);
                }
            }
        }
    }

    // write O (divide by l) as fp16 (attnproj A operand)
    {
        float li0 = 1.0f / l0, li1 = 1.0f / l1;
#pragma unroll
        for (int nj = 0; nj < 8; nj++) {
            int c = h * HD + nj * 8 + 2 * tig;
            *(__half2*)&y[(size_t)(b * TDIM + row0) * CDIM + c] =
                __floats2half2_rn(oacc[nj][0] * li0, oacc[nj][1] * li0);
            *(__half2*)&y[(size_t)(b * TDIM + row1) * CDIM + c] =
                __floats2half2_rn(oacc[nj][2] * li1, oacc[nj][3] * li1);
        }
    }

    // entropy: H_row = m + log(S) - W/S
    if (tig == 0) {
        hrow[warp * 16 + g]     = m0 + logf(l0) - w0 / l0;
        hrow[warp * 16 + g + 8] = m1 + logf(l1) - w1 / l1;
    }
    __syncthreads();
    if (tid == 0) {
        float tot = 0.f;
        for (int i = 0; i < 128; i++) tot += hrow[i];
        atomicAdd(&g_ent, tot);
    }
}

// ------------------------------------------------------------------
extern "C" void kernel_launch(void* const* d_in, const int* in_sizes, int n_in,
                              void* d_out, int out_size) {
    const float* x          = (const float*)d_in[0];
    const float* ln1_w      = (const float*)d_in[1];
    const float* ln1_b      = (const float*)d_in[2];
    const float* attn_w     = (const float*)d_in[3];
    const float* attn_b     = (const float*)d_in[4];
    const float* attnproj_w = (const float*)d_in[5];
    const float* attnproj_b = (const float*)d_in[6];
    const float* ln2_w      = (const float*)d_in[7];
    const float* ln2_b      = (const float*)d_in[8];
    const float* fc_w       = (const float*)d_in[9];
    const float* fc_b       = (const float*)d_in[10];
    const float* proj_w     = (const float*)d_in[11];
    const float* proj_b     = (const float*)d_in[12];
    float* out = (float*)d_out;

    __half *p_h, *p_qkv, *p_y, *p_m, *p_wh;
    float *p_x1;
    cudaGetSymbolAddress((void**)&p_h,   g_h);
    cudaGetSymbolAddress((void**)&p_qkv, g_qkv);
    cudaGetSymbolAddress((void**)&p_y,   g_y);
    cudaGetSymbolAddress((void**)&p_x1,  g_x1);
    cudaGetSymbolAddress((void**)&p_m,   g_m);
    cudaGetSymbolAddress((void**)&p_wh,  g_wh);

    static int gemm_smem = 6 * HBUF * 2;                          // 110592 B
    static int attn_smem = (128 * AST + 4 * KVN) * 2 + 128 * 4;   // ~56 KB
    cudaFuncSetAttribute(gemm_f16,
                         cudaFuncAttributeMaxDynamicSharedMemorySize, gemm_smem);
    cudaFuncSetAttribute(flash_attn_f16,
                         cudaFuncAttributeMaxDynamicSharedMemorySize, attn_smem);

    // RN-convert weights to fp16 once per launch
    tohalf_kernel<<<3145728 / 1024, 256>>>(attn_w,     p_wh + WR_ATTN,  3145728);
    tohalf_kernel<<<1048576 / 1024, 256>>>(attnproj_w, p_wh + WR_APROJ, 1048576);
    tohalf_kernel<<<4194304 / 1024, 256>>>(fc_w,       p_wh + WR_FC,    4194304);
    tohalf_kernel<<<4194304 / 1024, 256>>>(proj_w,     p_wh + WR_PROJ,  4194304);

    // h = LN1(x)  (fp16 out; zeroes g_ent)
    ln_kernel<<<BT, 256>>>(x, ln1_w, ln1_b, p_h, 1);

    // qkv = h @ attn_w^T + attn_b   (fp16 out -> attention operands)
    gemm_f16<<<dim3(QKVC / 128, BT / 128), 256, gemm_smem>>>(
        p_h, p_wh + WR_ATTN, attn_b, nullptr, p_qkv, BT, QKVC, CDIM, 0, 1);

    // attention (+entropy) -> y fp16
    flash_attn_f16<<<dim3(TDIM / 128, BH), 256, attn_smem>>>(p_qkv, p_y);

    // x1 = x + y @ attnproj_w^T + attnproj_b   (fp32 out)
    gemm_f16<<<dim3(CDIM / 128, BT / 128), 256, gemm_smem>>>(
        p_y, p_wh + WR_APROJ, attnproj_b, x, p_x1, BT, CDIM, CDIM, 0, 0);

    // h = LN2(x1)  (fp16 out)
    ln_kernel<<<BT, 256>>>(p_x1, ln2_w, ln2_b, p_h, 0);

    // m = gelu(h @ fc_w^T + fc_b)   (fp16 out)
    gemm_f16<<<dim3(FFC / 128, BT / 128), 256, gemm_smem>>>(
        p_h, p_wh + WR_FC, fc_b, nullptr, p_m, BT, FFC, CDIM, 1, 1);

    // out = x1 + m @ proj_w^T + proj_b   (fp32 out)
    gemm_f16<<<dim3(CDIM / 128, BT / 128), 256, gemm_smem>>>(
        p_m, p_wh + WR_PROJ, proj_b, p_x1, out, BT, CDIM, FFC, 0, 0);

    // entropy scalar
    finalize_kernel<<<1, 1>>>(out, out_size);
}

// round 16
// speedup vs baseline: 2.0382x; 1.0098x over previous
#include <cuda_runtime.h>
#include <cuda_fp16.h>
#include <math.h>
#include <stdint.h>

// Problem constants
#define BATCH 2
#define TDIM 2048
#define CDIM 1024
#define HN 16
#define HD 64
#define BT (BATCH * TDIM)        // 4096 rows
#define BH (BATCH * HN)          // 32 batch-heads
#define QKVC (3 * CDIM)          // 3072
#define FFC (4 * CDIM)           // 4096

#define NEG_BIG (-1e30f)
#define SCL (0.125f * 1.4426950408889634f)   // 1/sqrt(64) * log2(e)
#define RLOG2E 0.6931471805599453f           // ln(2)

// -------- scratch (static device globals; no allocation) ----------
__device__ __half g_h[BT * CDIM];
__device__ __half g_qkv[BT * QKVC];
__device__ __half g_y[BT * CDIM];
__device__ float  g_x1[BT * CDIM];
__device__ __half g_m[BT * FFC];
__device__ __half g_wh[12582912];      // fp16 weights: attn|attnproj|fc|proj
__device__ float  g_ent;

#define WR_ATTN  0
#define WR_APROJ 3145728
#define WR_FC    4194304
#define WR_PROJ  8388608
#define WR_TOT   12582912

// -------- helpers -------------------------------------------------
__device__ __forceinline__ void cp16(void* s, const void* g) {
    unsigned sa = (unsigned)__cvta_generic_to_shared(s);
    asm volatile("cp.async.cg.shared.global [%0], [%1], 16;" :: "r"(sa), "l"(g));
}
#define CP_COMMIT() asm volatile("cp.async.commit_group;")
#define CP_WAIT0()  asm volatile("cp.async.wait_group 0;")

__device__ __forceinline__ void mma_f16(float* c, const unsigned* a, const unsigned* b) {
    asm("mma.sync.aligned.m16n8k16.row.col.f32.f16.f16.f32 "
        "{%0,%1,%2,%3}, {%4,%5,%6,%7}, {%8,%9}, {%0,%1,%2,%3};"
        : "+f"(c[0]), "+f"(c[1]), "+f"(c[2]), "+f"(c[3])
        : "r"(a[0]), "r"(a[1]), "r"(a[2]), "r"(a[3]), "r"(b[0]), "r"(b[1]));
}

__device__ __forceinline__ void ldm_x4(unsigned* r, uint32_t addr) {
    asm volatile("ldmatrix.sync.aligned.m8n8.x4.shared.b16 {%0,%1,%2,%3}, [%4];"
        : "=r"(r[0]), "=r"(r[1]), "=r"(r[2]), "=r"(r[3]) : "r"(addr));
}

__device__ __forceinline__ unsigned pack_h2(float a, float b) {
    __half2 h = __floats2half2_rn(a, b);
    return *(unsigned*)&h;
}

// -------- merged weight conversion fp32 -> fp16 (RN) --------------
__global__ void tohalf_all_kernel(const float* __restrict__ w0,  // attn
                                  const float* __restrict__ w1,  // attnproj
                                  const float* __restrict__ w2,  // fc
                                  const float* __restrict__ w3,  // proj
                                  __half* __restrict__ out) {
    int i = (blockIdx.x * blockDim.x + threadIdx.x) * 4;
    if (i >= WR_TOT) return;
    const float* src;
    int off;
    if (i < WR_APROJ)      { src = w0; off = i; }
    else if (i < WR_FC)    { src = w1; off = i - WR_APROJ; }
    else if (i < WR_PROJ)  { src = w2; off = i - WR_FC; }
    else                   { src = w3; off = i - WR_PROJ; }
    float4 v = *(const float4*)&src[off];
    *(__half2*)&out[i]     = __floats2half2_rn(v.x, v.y);
    *(__half2*)&out[i + 2] = __floats2half2_rn(v.z, v.w);
}

// -------- LayerNorm: fp32 in, fp16 out (optionally zeroes g_ent) --
__global__ void ln_kernel(const float* __restrict__ x,
                          const float* __restrict__ w,
                          const float* __restrict__ b,
                          __half* __restrict__ out, int zent) {
    int row = blockIdx.x;
    int tid = threadIdx.x;
    int lane = tid & 31, warp = tid >> 5;
    if (zent && row == 0 && tid == 0) g_ent = 0.0f;
    const float* xr = x + (size_t)row * CDIM;
    __shared__ float rs[8], rq[8];

    float4 v = *(const float4*)&xr[tid * 4];
    float lsum = v.x + v.y + v.z + v.w;
    float lsq  = v.x * v.x + v.y * v.y + v.z * v.z + v.w * v.w;
#pragma unroll
    for (int o = 16; o > 0; o >>= 1) {
        lsum += __shfl_xor_sync(0xFFFFFFFFu, lsum, o);
        lsq  += __shfl_xor_sync(0xFFFFFFFFu, lsq, o);
    }
    if (lane == 0) { rs[warp] = lsum; rq[warp] = lsq; }
    __syncthreads();
    float tsum, tsq;
    {
        float a = rs[lane & 7], c = rq[lane & 7];
#pragma unroll
        for (int o = 4; o > 0; o >>= 1) {
            a += __shfl_xor_sync(0xFFFFFFFFu, a, o);
            c += __shfl_xor_sync(0xFFFFFFFFu, c, o);
        }
        tsum = a; tsq = c;
    }
    float mean = tsum * (1.0f / CDIM);
    float var = tsq * (1.0f / CDIM) - mean * mean;
    float rstd = rsqrtf(var + 1e-5f);

    float4 wv = *(const float4*)&w[tid * 4];
    float4 bv = *(const float4*)&b[tid * 4];
    __half2* orow = (__half2*)(out + (size_t)row * CDIM);
    orow[tid * 2] = __floats2half2_rn((v.x - mean) * rstd * wv.x + bv.x,
                                      (v.y - mean) * rstd * wv.y + bv.y);
    orow[tid * 2 + 1] = __floats2half2_rn((v.z - mean) * rstd * wv.z + bv.z,
                                          (v.w - mean) * rstd * wv.w + bv.w);
}

__device__ __forceinline__ float gelu_tanh(float x) {
    const float k0 = 0.7978845608028654f;
    const float k1 = 0.044715f;
    float u = k0 * (x + k1 * x * x * x);
    float t = __expf(2.0f * u);
    float th = (t - 1.0f) / (t + 1.0f);
    return 0.5f * x * (1.0f + th);
}

// -------- fp16 tensor-core GEMM: C = A[M,K]*W[N,K]^T + bias -------
// 128x128x64 tile, 256 threads, warp grid 2(m)x4(n), warp tile 64x32.
// entOut: if non-null, block (0,0) thread 0 writes entropy scalar.
#define HST 72                  // smem row stride in halfs (144B)
#define HBUF (128 * HST)

__global__ __launch_bounds__(256, 2)
void gemm_f16(const __half* __restrict__ A, const __half* __restrict__ W,
              const float* __restrict__ bias, const float* __restrict__ resid,
              void* __restrict__ Cv, int M, int N, int K,
              int act, int outHalf, float* entOut) {
    extern __shared__ __half hsm[];
    __half* As = hsm;                   // [3][128][72]
    __half* Ws = hsm + 3 * HBUF;        // [3][128][72]

    int tid = threadIdx.x;
    int warp = tid >> 5, lane = tid & 31;
    int wm = warp >> 2, wn = warp & 3;
    int g = lane >> 2, tig = lane & 3;
    int rowBase = blockIdx.y * 128, colBase = blockIdx.x * 128;
    const __half* Ap = A + (size_t)rowBase * K;
    const __half* Wp = W + (size_t)colBase * K;

    if (entOut && blockIdx.x == 0 && blockIdx.y == 0 && tid == 0)
        entOut[0] = g_ent * (1.0f / (float)(BH * TDIM));

    uint32_t as_u32 = (uint32_t)__cvta_generic_to_shared(As);
    uint32_t ws_u32 = (uint32_t)__cvta_generic_to_shared(Ws);
    uint32_t a_lm = (uint32_t)((wm * 64 + (lane & 15)) * HST + (lane >> 4) * 8);
    uint32_t b_lm = (uint32_t)((wn * 32 + (lane & 7) + ((lane >> 4) << 3)) * HST
                               + ((lane >> 3) & 1) * 8);

    float acc[4][4][4];
#pragma unroll
    for (int i = 0; i < 4; i++)
#pragma unroll
        for (int j = 0; j < 4; j++)
#pragma unroll
            for (int p = 0; p < 4; p++) acc[i][j][p] = 0.f;

    // prologue: stage tiles 0 and 1
#pragma unroll
    for (int pt = 0; pt < 2; pt++) {
        int kt = pt * 64;
#pragma unroll
        for (int i = 0; i < 4; i++) {
            int idx = tid + i * 256;
            int r = idx >> 3, c = (idx & 7) * 8;
            cp16(&As[pt * HBUF + r * HST + c], Ap + (size_t)r * K + kt + c);
            cp16(&Ws[pt * HBUF + r * HST + c], Wp + (size_t)r * K + kt + c);
        }
        CP_COMMIT();
    }

    int nt = K >> 6;
    int buf = 0;
    for (int t = 0; t < nt; t++) {
        if (t == nt - 1) asm volatile("cp.async.wait_group 0;" ::: "memory");
        else             asm volatile("cp.async.wait_group 1;" ::: "memory");
        __syncthreads();
        if (t + 2 < nt) {
            int kt = (t + 2) * 64;
            int nb = buf >= 1 ? buf - 1 : buf + 2;   // (t+2)%3
#pragma unroll
            for (int i = 0; i < 4; i++) {
                int idx = tid + i * 256;
                int r = idx >> 3, c = (idx & 7) * 8;
                cp16(&As[nb * HBUF + r * HST + c], Ap + (size_t)r * K + kt + c);
                cp16(&Ws[nb * HBUF + r * HST + c], Wp + (size_t)r * K + kt + c);
            }
            CP_COMMIT();
        }
        uint32_t aaddr = as_u32 + (uint32_t)(buf * HBUF + a_lm) * 2;
        uint32_t baddr = ws_u32 + (uint32_t)(buf * HBUF + b_lm) * 2;
#pragma unroll
        for (int ks = 0; ks < 4; ks++) {
            int k0 = ks * 16;
            unsigned af[4][4], bf[4][2];
#pragma unroll
            for (int mi = 0; mi < 4; mi++)
                ldm_x4(af[mi], aaddr + (uint32_t)((mi * 16 * HST + k0) * 2));
#pragma unroll
            for (int njp = 0; njp < 2; njp++) {
                unsigned tmp[4];
                ldm_x4(tmp, baddr + (uint32_t)((njp * 16 * HST + k0) * 2));
                bf[2 * njp][0] = tmp[0];     bf[2 * njp][1] = tmp[1];
                bf[2 * njp + 1][0] = tmp[2]; bf[2 * njp + 1][1] = tmp[3];
            }
#pragma unroll
            for (int mi = 0; mi < 4; mi++)
#pragma unroll
                for (int nj = 0; nj < 4; nj++)
                    mma_f16(acc[mi][nj], af[mi], bf[nj]);
        }
        buf = buf < 2 ? buf + 1 : 0;
    }

    // epilogue
    float* Cf = (float*)Cv;
    __half* Ch = (__half*)Cv;
#pragma unroll
    for (int mi = 0; mi < 4; mi++) {
#pragma unroll
        for (int h2 = 0; h2 < 2; h2++) {
            int r = rowBase + wm * 64 + mi * 16 + g + h2 * 8;
            const float* rrow = resid ? resid + (size_t)r * N : nullptr;
#pragma unroll
            for (int nj = 0; nj < 4; nj++) {
                int c = colBase + wn * 32 + nj * 8 + 2 * tig;
                float v0 = acc[mi][nj][h2 * 2]     + bias[c];
                float v1 = acc[mi][nj][h2 * 2 + 1] + bias[c + 1];
                if (act == 1) { v0 = gelu_tanh(v0); v1 = gelu_tanh(v1); }
                if (rrow) { v0 += rrow[c]; v1 += rrow[c + 1]; }
                if (outHalf) {
                    *(__half2*)&Ch[(size_t)r * N + c] = __floats2half2_rn(v0, v1);
                } else {
                    *(float2*)&Cf[(size_t)r * N + c] = make_float2(v0, v1);
                }
            }
        }
    }
}

// -------- fp16 flash attention: 128q x 64k tiles -------------------
// P in registers; exp2-domain softmax (log2e folded into score scale).
#define AST 72
#define KVN (64 * AST)

__global__ __launch_bounds__(256, 2)
void flash_attn_f16(const __half* __restrict__ qkv, __half* __restrict__ y) {
    extern __shared__ __half hs[];
    __half* Qs = hs;                     // [128][72]
    __half* Ks = Qs + 128 * AST;         // [2][64][72]
    __half* Vs = Ks + 2 * KVN;           // [2][64][72]
    float* hrow = (float*)(Vs + 2 * KVN);// [128]

    int tid = threadIdx.x;
    int warp = tid >> 5, lane = tid & 31;
    int g = lane >> 2, tig = lane & 3;
    int qt = (TDIM / 128 - 1) - blockIdx.x;   // long tiles first
    int bh = blockIdx.y;
    int b = bh >> 4, h = bh & 15;
    int qb = qt * 128;
    const __half* base = qkv + (size_t)b * TDIM * QKVC + h * HD;

    // prefetch Q (128x64) + K0 + V0
#pragma unroll
    for (int i = 0; i < 4; i++) {
        int idx = tid + i * 256;
        int r = idx >> 3, c = (idx & 7) * 8;
        cp16(&Qs[r * AST + c], &base[(size_t)(qb + r) * QKVC + c]);
    }
#pragma unroll
    for (int i = 0; i < 2; i++) {
        int idx = tid + i * 256;
        int r = idx >> 3, c = (idx & 7) * 8;
        cp16(&Ks[r * AST + c], &base[(size_t)r * QKVC + CDIM + c]);
        cp16(&Vs[r * AST + c], &base[(size_t)r * QKVC + 2 * CDIM + c]);
    }
    CP_COMMIT();
    CP_WAIT0();
    __syncthreads();

    uint32_t qs_u32 = (uint32_t)__cvta_generic_to_shared(Qs);
    uint32_t ks_u32 = (uint32_t)__cvta_generic_to_shared(Ks);
    uint32_t vs_u32 = (uint32_t)__cvta_generic_to_shared(Vs);
    uint32_t q_lm = (uint32_t)((warp * 16 + (lane & 15)) * AST + (lane >> 4) * 8);
    uint32_t k_lm = (uint32_t)(((lane & 7) + ((lane >> 4) << 3)) * AST
                               + ((lane >> 3) & 1) * 8);
    uint32_t v_lm = (uint32_t)(((lane & 15) * AST + (lane >> 4) * 8) * 2);

    unsigned qf[4][4];
#pragma unroll
    for (int ks = 0; ks < 4; ks++)
        ldm_x4(qf[ks], qs_u32 + (q_lm + ks * 16) * 2);

    // all softmax state in log2 domain
    float m0 = NEG_BIG, m1 = NEG_BIG, l0 = 0.f, l1 = 0.f, w0 = 0.f, w1 = 0.f;
    float oacc[8][4];
#pragma unroll
    for (int nj = 0; nj < 8; nj++)
#pragma unroll
        for (int p = 0; p < 4; p++) oacc[nj][p] = 0.f;

    int row0 = qb + warp * 16 + g, row1 = row0 + 8;
    int ni = 2 * qt + 2;

    for (int i = 0; i < ni; i++) {
        CP_WAIT0();
        __syncthreads();
        if (i + 1 < ni) {
            int nb = (i + 1) & 1, kb2 = (i + 1) * 64;
#pragma unroll
            for (int it = 0; it < 2; it++) {
                int idx = tid + it * 256;
                int r = idx >> 3, c = (idx & 7) * 8;
                cp16(&Ks[nb * KVN + r * AST + c],
                     &base[(size_t)(kb2 + r) * QKVC + CDIM + c]);
                cp16(&Vs[nb * KVN + r * AST + c],
                     &base[(size_t)(kb2 + r) * QKVC + 2 * CDIM + c]);
            }
            CP_COMMIT();
        }
        int kb = i * 64;
        if (qb + warp * 16 + 15 >= kb) {
            uint32_t kaddr = ks_u32 + (uint32_t)((i & 1) * KVN + k_lm) * 2;

            // ---- S = Q K^T ----
            float sacc[8][4];
#pragma unroll
            for (int nj = 0; nj < 8; nj++)
#pragma unroll
                for (int p = 0; p < 4; p++) sacc[nj][p] = 0.f;
#pragma unroll
            for (int ks = 0; ks < 4; ks++) {
#pragma unroll
                for (int njp = 0; njp < 4; njp++) {
                    unsigned tmp[4];
                    ldm_x4(tmp, kaddr + (uint32_t)((njp * 16 * AST + ks * 16) * 2));
                    unsigned bfa[2] = {tmp[0], tmp[1]};
                    unsigned bfb[2] = {tmp[2], tmp[3]};
                    mma_f16(sacc[2 * njp], qf[ks], bfa);
                    mma_f16(sacc[2 * njp + 1], qf[ks], bfb);
                }
            }

            // ---- scale (log2 domain) + mask + row max ----
            float mx0 = NEG_BIG, mx1 = NEG_BIG;
#pragma unroll
            for (int nj = 0; nj < 8; nj++) {
                int cg = kb + nj * 8 + 2 * tig;
                float s0 = sacc[nj][0] * SCL;
                float s1 = sacc[nj][1] * SCL;
                float s2 = sacc[nj][2] * SCL;
                float s3 = sacc[nj][3] * SCL;
                if (cg > row0) s0 = NEG_BIG;
                if (cg + 1 > row0) s1 = NEG_BIG;
                if (cg > row1) s2 = NEG_BIG;
                if (cg + 1 > row1) s3 = NEG_BIG;
                sacc[nj][0] = s0; sacc[nj][1] = s1;
                sacc[nj][2] = s2; sacc[nj][3] = s3;
                mx0 = fmaxf(mx0, fmaxf(s0, s1));
                mx1 = fmaxf(mx1, fmaxf(s2, s3));
            }
            mx0 = fmaxf(mx0, __shfl_xor_sync(0xFFFFFFFFu, mx0, 1));
            mx0 = fmaxf(mx0, __shfl_xor_sync(0xFFFFFFFFu, mx0, 2));
            mx1 = fmaxf(mx1, __shfl_xor_sync(0xFFFFFFFFu, mx1, 1));
            mx1 = fmaxf(mx1, __shfl_xor_sync(0xFFFFFFFFu, mx1, 2));
            float mn0 = fmaxf(m0, mx0), mn1 = fmaxf(m1, mx1);

            // ---- exp2 + sums; P packed to fp16 A-fragments ----
            unsigned pe[8][2];
            float se0 = 0.f, se1 = 0.f, sw0 = 0.f, sw1 = 0.f;
#pragma unroll
            for (int nj = 0; nj < 8; nj++) {
                float s0 = sacc[nj][0], s1 = sacc[nj][1];
                float s2 = sacc[nj][2], s3 = sacc[nj][3];
                float e0 = exp2f(s0 - mn0), e1 = exp2f(s1 - mn0);
                float e2 = exp2f(s2 - mn1), e3 = exp2f(s3 - mn1);
                se0 += e0 + e1; sw0 += e0 * s0 + e1 * s1;
                se1 += e2 + e3; sw1 += e2 * s2 + e3 * s3;
                pe[nj][0] = pack_h2(e0, e1);
                pe[nj][1] = pack_h2(e2, e3);
            }
            se0 += __shfl_xor_sync(0xFFFFFFFFu, se0, 1);
            se0 += __shfl_xor_sync(0xFFFFFFFFu, se0, 2);
            sw0 += __shfl_xor_sync(0xFFFFFFFFu, sw0, 1);
            sw0 += __shfl_xor_sync(0xFFFFFFFFu, sw0, 2);
            se1 += __shfl_xor_sync(0xFFFFFFFFu, se1, 1);
            se1 += __shfl_xor_sync(0xFFFFFFFFu, se1, 2);
            sw1 += __shfl_xor_sync(0xFFFFFFFFu, sw1, 1);
            sw1 += __shfl_xor_sync(0xFFFFFFFFu, sw1, 2);

            float c0f = exp2f(m0 - mn0), c1f = exp2f(m1 - mn1);
            l0 = l0 * c0f + se0; w0 = w0 * c0f + sw0; m0 = mn0;
            l1 = l1 * c1f + se1; w1 = w1 * c1f + sw1; m1 = mn1;
#pragma unroll
            for (int nj = 0; nj < 8; nj++) {
                oacc[nj][0] *= c0f; oacc[nj][1] *= c0f;
                oacc[nj][2] *= c1f; oacc[nj][3] *= c1f;
            }

            // ---- O += P V ----
            uint32_t vbase = vs_u32 + (uint32_t)((i & 1) * KVN * 2) + v_lm;
#pragma unroll
            for (int ks = 0; ks < 4; ks++) {
                unsigned af[4] = { pe[2 * ks][0], pe[2 * ks][1],
                                   pe[2 * ks + 1][0], pe[2 * ks + 1][1] };
#pragma unroll
                for (int dj = 0; dj < 4; dj++) {
                    uint32_t addr = vbase + (uint32_t)((ks * 16 * AST + dj * 16) * 2);
                    unsigned v0, v1, v2, v3;
                    asm volatile(
                        "ldmatrix.sync.aligned.m8n8.x4.trans.shared.b16 "
                        "{%0,%1,%2,%3}, [%4];"
                        : "=r"(v0), "=r"(v1), "=r"(v2), "=r"(v3) : "r"(addr));
                    unsigned bfa[2] = {v0, v1};
                    unsigned bfb[2] = {v2, v3};
                    mma_f16(oacc[2 * dj], af, bfa);
                    mma_f16(oacc[2 * dj + 1], af, bfb);
                }
            }
        }
    }

    // write O (divide by l) as fp16
    {
        float li0 = 1.0f / l0, li1 = 1.0f / l1;
#pragma unroll
        for (int nj = 0; nj < 8; nj++) {
            int c = h * HD + nj * 8 + 2 * tig;
            *(__half2*)&y[(size_t)(b * TDIM + row0) * CDIM + c] =
                __floats2half2_rn(oacc[nj][0] * li0, oacc[nj][1] * li0);
            *(__half2*)&y[(size_t)(b * TDIM + row1) * CDIM + c] =
                __floats2half2_rn(oacc[nj][2] * li1, oacc[nj][3] * li1);
        }
    }

    // entropy: log2-domain state -> H = (m' - W'/l)*ln2 + ln(l)
    if (tig == 0) {
        hrow[warp * 16 + g]     = (m0 - w0 / l0) * RLOG2E + logf(l0);
        hrow[warp * 16 + g + 8] = (m1 - w1 / l1) * RLOG2E + logf(l1);
    }
    __syncthreads();
    if (tid == 0) {
        float tot = 0.f;
        for (int i = 0; i < 128; i++) tot += hrow[i];
        atomicAdd(&g_ent, tot);
    }
}

// ------------------------------------------------------------------
extern "C" void kernel_launch(void* const* d_in, const int* in_sizes, int n_in,
                              void* d_out, int out_size) {
    const float* x          = (const float*)d_in[0];
    const float* ln1_w      = (const float*)d_in[1];
    const float* ln1_b      = (const float*)d_in[2];
    const float* attn_w     = (const float*)d_in[3];
    const float* attn_b     = (const float*)d_in[4];
    const float* attnproj_w = (const float*)d_in[5];
    const float* attnproj_b = (const float*)d_in[6];
    const float* ln2_w      = (const float*)d_in[7];
    const float* ln2_b      = (const float*)d_in[8];
    const float* fc_w       = (const float*)d_in[9];
    const float* fc_b       = (const float*)d_in[10];
    const float* proj_w     = (const float*)d_in[11];
    const float* proj_b     = (const float*)d_in[12];
    float* out = (float*)d_out;

    __half *p_h, *p_qkv, *p_y, *p_m, *p_wh;
    float *p_x1;
    cudaGetSymbolAddress((void**)&p_h,   g_h);
    cudaGetSymbolAddress((void**)&p_qkv, g_qkv);
    cudaGetSymbolAddress((void**)&p_y,   g_y);
    cudaGetSymbolAddress((void**)&p_x1,  g_x1);
    cudaGetSymbolAddress((void**)&p_m,   g_m);
    cudaGetSymbolAddress((void**)&p_wh,  g_wh);

    static int gemm_smem = 6 * HBUF * 2;                          // 110592 B
    static int attn_smem = (128 * AST + 4 * KVN) * 2 + 128 * 4;   // ~56 KB
    cudaFuncSetAttribute(gemm_f16,
                         cudaFuncAttributeMaxDynamicSharedMemorySize, gemm_smem);
    cudaFuncSetAttribute(flash_attn_f16,
                         cudaFuncAttributeMaxDynamicSharedMemorySize, attn_smem);

    float* entOut = (out_size > BT * CDIM) ? out + BT * CDIM : nullptr;

    // RN-convert all weights to fp16 in one launch
    tohalf_all_kernel<<<WR_TOT / 1024, 256>>>(attn_w, attnproj_w, fc_w, proj_w, p_wh);

    // h = LN1(x)  (fp16 out; zeroes g_ent)
    ln_kernel<<<BT, 256>>>(x, ln1_w, ln1_b, p_h, 1);

    // qkv = h @ attn_w^T + attn_b   (fp16 out)
    gemm_f16<<<dim3(QKVC / 128, BT / 128), 256, gemm_smem>>>(
        p_h, p_wh + WR_ATTN, attn_b, nullptr, p_qkv, BT, QKVC, CDIM, 0, 1, nullptr);

    // attention (+entropy) -> y fp16
    flash_attn_f16<<<dim3(TDIM / 128, BH), 256, attn_smem>>>(p_qkv, p_y);

    // x1 = x + y @ attnproj_w^T + attnproj_b   (fp32 out)
    gemm_f16<<<dim3(CDIM / 128, BT / 128), 256, gemm_smem>>>(
        p_y, p_wh + WR_APROJ, attnproj_b, x, p_x1, BT, CDIM, CDIM, 0, 0, nullptr);

    // h = LN2(x1)  (fp16 out)
    ln_kernel<<<BT, 256>>>(p_x1, ln2_w, ln2_b, p_h, 0);

    // m = gelu(h @ fc_w^T + fc_b)   (fp16 out)
    gemm_f16<<<dim3(FFC / 128, BT / 128), 256, gemm_smem>>>(
        p_h, p_wh + WR_FC, fc_b, nullptr, p_m, BT, FFC, CDIM, 1, 1, nullptr);

    // out = x1 + m @ proj_w^T + proj_b   (fp32 out; writes entropy scalar)
    gemm_f16<<<dim3(CDIM / 128, BT / 128), 256, gemm_smem>>>(
        p_m, p_wh + WR_PROJ, proj_b, p_x1, out, BT, CDIM, FFC, 0, 0, entOut);
}

// round 17
// speedup vs baseline: 2.0617x; 1.0115x over previous
#include <cuda_runtime.h>
#include <cuda_fp16.h>
#include <math.h>
#include <stdint.h>

// Problem constants
#define BATCH 2
#define TDIM 2048
#define CDIM 1024
#define HN 16
#define HD 64
#define BT (BATCH * TDIM)        // 4096 rows
#define BH (BATCH * HN)          // 32 batch-heads
#define QKVC (3 * CDIM)          // 3072
#define FFC (4 * CDIM)           // 4096

#define NEG_BIG (-1e30f)
#define SCL (0.125f * 1.4426950408889634f)   // 1/sqrt(64) * log2(e)
#define RLOG2E 0.6931471805599453f           // ln(2)

// -------- scratch (static device globals; no allocation) ----------
__device__ __half g_h[BT * CDIM];
__device__ __half g_qkv[BT * QKVC];
__device__ __half g_y[BT * CDIM];
__device__ float  g_x1[BT * CDIM];
__device__ __half g_m[BT * FFC];
__device__ __half g_wh[12582912];      // fp16 weights: attn|attnproj|fc|proj
__device__ float  g_ent;

#define WR_ATTN  0
#define WR_APROJ 3145728
#define WR_FC    4194304
#define WR_PROJ  8388608
#define WR_TOT   12582912

// -------- helpers -------------------------------------------------
__device__ __forceinline__ void cp16(void* s, const void* g) {
    unsigned sa = (unsigned)__cvta_generic_to_shared(s);
    asm volatile("cp.async.cg.shared.global [%0], [%1], 16;" :: "r"(sa), "l"(g));
}
#define CP_COMMIT() asm volatile("cp.async.commit_group;")
#define CP_WAIT0()  asm volatile("cp.async.wait_group 0;")

__device__ __forceinline__ void mma_f16(float* c, const unsigned* a, const unsigned* b) {
    asm("mma.sync.aligned.m16n8k16.row.col.f32.f16.f16.f32 "
        "{%0,%1,%2,%3}, {%4,%5,%6,%7}, {%8,%9}, {%0,%1,%2,%3};"
        : "+f"(c[0]), "+f"(c[1]), "+f"(c[2]), "+f"(c[3])
        : "r"(a[0]), "r"(a[1]), "r"(a[2]), "r"(a[3]), "r"(b[0]), "r"(b[1]));
}

__device__ __forceinline__ void ldm_x4(unsigned* r, uint32_t addr) {
    asm volatile("ldmatrix.sync.aligned.m8n8.x4.shared.b16 {%0,%1,%2,%3}, [%4];"
        : "=r"(r[0]), "=r"(r[1]), "=r"(r[2]), "=r"(r[3]) : "r"(addr));
}

__device__ __forceinline__ unsigned pack_h2(float a, float b) {
    __half2 h = __floats2half2_rn(a, b);
    return *(unsigned*)&h;
}

// -------- merged weight conversion fp32 -> fp16 (RN) --------------
__global__ void tohalf_all_kernel(const float* __restrict__ w0,
                                  const float* __restrict__ w1,
                                  const float* __restrict__ w2,
                                  const float* __restrict__ w3,
                                  __half* __restrict__ out) {
    int i = (blockIdx.x * blockDim.x + threadIdx.x) * 4;
    if (i >= WR_TOT) return;
    const float* src;
    int off;
    if (i < WR_APROJ)      { src = w0; off = i; }
    else if (i < WR_FC)    { src = w1; off = i - WR_APROJ; }
    else if (i < WR_PROJ)  { src = w2; off = i - WR_FC; }
    else                   { src = w3; off = i - WR_PROJ; }
    float4 v = *(const float4*)&src[off];
    *(__half2*)&out[i]     = __floats2half2_rn(v.x, v.y);
    *(__half2*)&out[i + 2] = __floats2half2_rn(v.z, v.w);
}

// -------- LayerNorm: fp32 in, fp16 out (optionally zeroes g_ent) --
__global__ void ln_kernel(const float* __restrict__ x,
                          const float* __restrict__ w,
                          const float* __restrict__ b,
                          __half* __restrict__ out, int zent) {
    int row = blockIdx.x;
    int tid = threadIdx.x;
    int lane = tid & 31, warp = tid >> 5;
    if (zent && row == 0 && tid == 0) g_ent = 0.0f;
    const float* xr = x + (size_t)row * CDIM;
    __shared__ float rs[8], rq[8];

    float4 v = *(const float4*)&xr[tid * 4];
    float lsum = v.x + v.y + v.z + v.w;
    float lsq  = v.x * v.x + v.y * v.y + v.z * v.z + v.w * v.w;
#pragma unroll
    for (int o = 16; o > 0; o >>= 1) {
        lsum += __shfl_xor_sync(0xFFFFFFFFu, lsum, o);
        lsq  += __shfl_xor_sync(0xFFFFFFFFu, lsq, o);
    }
    if (lane == 0) { rs[warp] = lsum; rq[warp] = lsq; }
    __syncthreads();
    float tsum, tsq;
    {
        float a = rs[lane & 7], c = rq[lane & 7];
#pragma unroll
        for (int o = 4; o > 0; o >>= 1) {
            a += __shfl_xor_sync(0xFFFFFFFFu, a, o);
            c += __shfl_xor_sync(0xFFFFFFFFu, c, o);
        }
        tsum = a; tsq = c;
    }
    float mean = tsum * (1.0f / CDIM);
    float var = tsq * (1.0f / CDIM) - mean * mean;
    float rstd = rsqrtf(var + 1e-5f);

    float4 wv = *(const float4*)&w[tid * 4];
    float4 bv = *(const float4*)&b[tid * 4];
    __half2* orow = (__half2*)(out + (size_t)row * CDIM);
    orow[tid * 2] = __floats2half2_rn((v.x - mean) * rstd * wv.x + bv.x,
                                      (v.y - mean) * rstd * wv.y + bv.y);
    orow[tid * 2 + 1] = __floats2half2_rn((v.z - mean) * rstd * wv.z + bv.z,
                                          (v.w - mean) * rstd * wv.w + bv.w);
}

__device__ __forceinline__ float gelu_tanh(float x) {
    const float k0 = 0.7978845608028654f;
    const float k1 = 0.044715f;
    float u = k0 * (x + k1 * x * x * x);
    float t = __expf(2.0f * u);
    float th = (t - 1.0f) / (t + 1.0f);
    return 0.5f * x * (1.0f + th);
}

// -------- fp16 tensor-core GEMM: C = A[M,K]*W[N,K]^T + bias -------
#define HST 72
#define HBUF (128 * HST)

__global__ __launch_bounds__(256, 2)
void gemm_f16(const __half* __restrict__ A, const __half* __restrict__ W,
              const float* __restrict__ bias, const float* __restrict__ resid,
              void* __restrict__ Cv, int M, int N, int K,
              int act, int outHalf, float* entOut) {
    extern __shared__ __half hsm[];
    __half* As = hsm;                   // [3][128][72]
    __half* Ws = hsm + 3 * HBUF;        // [3][128][72]

    int tid = threadIdx.x;
    int warp = tid >> 5, lane = tid & 31;
    int wm = warp >> 2, wn = warp & 3;
    int g = lane >> 2, tig = lane & 3;
    int rowBase = blockIdx.y * 128, colBase = blockIdx.x * 128;
    const __half* Ap = A + (size_t)rowBase * K;
    const __half* Wp = W + (size_t)colBase * K;

    if (entOut && blockIdx.x == 0 && blockIdx.y == 0 && tid == 0)
        entOut[0] = g_ent * (1.0f / (float)(BH * TDIM));

    uint32_t as_u32 = (uint32_t)__cvta_generic_to_shared(As);
    uint32_t ws_u32 = (uint32_t)__cvta_generic_to_shared(Ws);
    uint32_t a_lm = (uint32_t)((wm * 64 + (lane & 15)) * HST + (lane >> 4) * 8);
    uint32_t b_lm = (uint32_t)((wn * 32 + (lane & 7) + ((lane >> 4) << 3)) * HST
                               + ((lane >> 3) & 1) * 8);

    float acc[4][4][4];
#pragma unroll
    for (int i = 0; i < 4; i++)
#pragma unroll
        for (int j = 0; j < 4; j++)
#pragma unroll
            for (int p = 0; p < 4; p++) acc[i][j][p] = 0.f;

#pragma unroll
    for (int pt = 0; pt < 2; pt++) {
        int kt = pt * 64;
#pragma unroll
        for (int i = 0; i < 4; i++) {
            int idx = tid + i * 256;
            int r = idx >> 3, c = (idx & 7) * 8;
            cp16(&As[pt * HBUF + r * HST + c], Ap + (size_t)r * K + kt + c);
            cp16(&Ws[pt * HBUF + r * HST + c], Wp + (size_t)r * K + kt + c);
        }
        CP_COMMIT();
    }

    int nt = K >> 6;
    int buf = 0;
    for (int t = 0; t < nt; t++) {
        if (t == nt - 1) asm volatile("cp.async.wait_group 0;" ::: "memory");
        else             asm volatile("cp.async.wait_group 1;" ::: "memory");
        __syncthreads();
        if (t + 2 < nt) {
            int kt = (t + 2) * 64;
            int nb = buf >= 1 ? buf - 1 : buf + 2;   // (t+2)%3
#pragma unroll
            for (int i = 0; i < 4; i++) {
                int idx = tid + i * 256;
                int r = idx >> 3, c = (idx & 7) * 8;
                cp16(&As[nb * HBUF + r * HST + c], Ap + (size_t)r * K + kt + c);
                cp16(&Ws[nb * HBUF + r * HST + c], Wp + (size_t)r * K + kt + c);
            }
            CP_COMMIT();
        }
        uint32_t aaddr = as_u32 + (uint32_t)(buf * HBUF + a_lm) * 2;
        uint32_t baddr = ws_u32 + (uint32_t)(buf * HBUF + b_lm) * 2;
#pragma unroll
        for (int ks = 0; ks < 4; ks++) {
            int k0 = ks * 16;
            unsigned af[4][4], bf[4][2];
#pragma unroll
            for (int mi = 0; mi < 4; mi++)
                ldm_x4(af[mi], aaddr + (uint32_t)((mi * 16 * HST + k0) * 2));
#pragma unroll
            for (int njp = 0; njp < 2; njp++) {
                unsigned tmp[4];
                ldm_x4(tmp, baddr + (uint32_t)((njp * 16 * HST + k0) * 2));
                bf[2 * njp][0] = tmp[0];     bf[2 * njp][1] = tmp[1];
                bf[2 * njp + 1][0] = tmp[2]; bf[2 * njp + 1][1] = tmp[3];
            }
#pragma unroll
            for (int mi = 0; mi < 4; mi++)
#pragma unroll
                for (int nj = 0; nj < 4; nj++)
                    mma_f16(acc[mi][nj], af[mi], bf[nj]);
        }
        buf = buf < 2 ? buf + 1 : 0;
    }

    float* Cf = (float*)Cv;
    __half* Ch = (__half*)Cv;
#pragma unroll
    for (int mi = 0; mi < 4; mi++) {
#pragma unroll
        for (int h2 = 0; h2 < 2; h2++) {
            int r = rowBase + wm * 64 + mi * 16 + g + h2 * 8;
            const float* rrow = resid ? resid + (size_t)r * N : nullptr;
#pragma unroll
            for (int nj = 0; nj < 4; nj++) {
                int c = colBase + wn * 32 + nj * 8 + 2 * tig;
                float v0 = acc[mi][nj][h2 * 2]     + bias[c];
                float v1 = acc[mi][nj][h2 * 2 + 1] + bias[c + 1];
                if (act == 1) { v0 = gelu_tanh(v0); v1 = gelu_tanh(v1); }
                if (rrow) { v0 += rrow[c]; v1 += rrow[c + 1]; }
                if (outHalf) {
                    *(__half2*)&Ch[(size_t)r * N + c] = __floats2half2_rn(v0, v1);
                } else {
                    *(float2*)&Cf[(size_t)r * N + c] = make_float2(v0, v1);
                }
            }
        }
    }
}

// -------- fp16 flash attention: 128q x 64k tiles -------------------
// Tile-level mask specialization: full mask path only when the tile
// crosses the warp's diagonal (<=2 tiles per warp).
#define AST 72
#define KVN (64 * AST)

__global__ __launch_bounds__(256, 2)
void flash_attn_f16(const __half* __restrict__ qkv, __half* __restrict__ y) {
    extern __shared__ __half hs[];
    __half* Qs = hs;                     // [128][72]
    __half* Ks = Qs + 128 * AST;         // [2][64][72]
    __half* Vs = Ks + 2 * KVN;           // [2][64][72]
    float* hrow = (float*)(Vs + 2 * KVN);// [128]

    int tid = threadIdx.x;
    int warp = tid >> 5, lane = tid & 31;
    int g = lane >> 2, tig = lane & 3;
    int qt = (TDIM / 128 - 1) - blockIdx.x;   // long tiles first
    int bh = blockIdx.y;
    int b = bh >> 4, h = bh & 15;
    int qb = qt * 128;
    const __half* base = qkv + (size_t)b * TDIM * QKVC + h * HD;

#pragma unroll
    for (int i = 0; i < 4; i++) {
        int idx = tid + i * 256;
        int r = idx >> 3, c = (idx & 7) * 8;
        cp16(&Qs[r * AST + c], &base[(size_t)(qb + r) * QKVC + c]);
    }
#pragma unroll
    for (int i = 0; i < 2; i++) {
        int idx = tid + i * 256;
        int r = idx >> 3, c = (idx & 7) * 8;
        cp16(&Ks[r * AST + c], &base[(size_t)r * QKVC + CDIM + c]);
        cp16(&Vs[r * AST + c], &base[(size_t)r * QKVC + 2 * CDIM + c]);
    }
    CP_COMMIT();
    CP_WAIT0();
    __syncthreads();

    uint32_t qs_u32 = (uint32_t)__cvta_generic_to_shared(Qs);
    uint32_t ks_u32 = (uint32_t)__cvta_generic_to_shared(Ks);
    uint32_t vs_u32 = (uint32_t)__cvta_generic_to_shared(Vs);
    uint32_t q_lm = (uint32_t)((warp * 16 + (lane & 15)) * AST + (lane >> 4) * 8);
    uint32_t k_lm = (uint32_t)(((lane & 7) + ((lane >> 4) << 3)) * AST
                               + ((lane >> 3) & 1) * 8);
    uint32_t v_lm = (uint32_t)(((lane & 15) * AST + (lane >> 4) * 8) * 2);

    unsigned qf[4][4];
#pragma unroll
    for (int ks = 0; ks < 4; ks++)
        ldm_x4(qf[ks], qs_u32 + (q_lm + ks * 16) * 2);

    float m0 = NEG_BIG, m1 = NEG_BIG, l0 = 0.f, l1 = 0.f, w0 = 0.f, w1 = 0.f;
    float oacc[8][4];
#pragma unroll
    for (int nj = 0; nj < 8; nj++)
#pragma unroll
        for (int p = 0; p < 4; p++) oacc[nj][p] = 0.f;

    int wrow = qb + warp * 16;           // warp's first q row
    int row0 = wrow + g, row1 = row0 + 8;
    int ni = 2 * qt + 2;

    for (int i = 0; i < ni; i++) {
        CP_WAIT0();
        __syncthreads();
        if (i + 1 < ni) {
            int nb = (i + 1) & 1, kb2 = (i + 1) * 64;
#pragma unroll
            for (int it = 0; it < 2; it++) {
                int idx = tid + it * 256;
                int r = idx >> 3, c = (idx & 7) * 8;
                cp16(&Ks[nb * KVN + r * AST + c],
                     &base[(size_t)(kb2 + r) * QKVC + CDIM + c]);
                cp16(&Vs[nb * KVN + r * AST + c],
                     &base[(size_t)(kb2 + r) * QKVC + 2 * CDIM + c]);
            }
            CP_COMMIT();
        }
        int kb = i * 64;
        if (wrow + 15 >= kb) {
            uint32_t kaddr = ks_u32 + (uint32_t)((i & 1) * KVN + k_lm) * 2;

            // ---- S = Q K^T ----
            float sacc[8][4];
#pragma unroll
            for (int nj = 0; nj < 8; nj++)
#pragma unroll
                for (int p = 0; p < 4; p++) sacc[nj][p] = 0.f;
#pragma unroll
            for (int ks = 0; ks < 4; ks++) {
#pragma unroll
                for (int njp = 0; njp < 4; njp++) {
                    unsigned tmp[4];
                    ldm_x4(tmp, kaddr + (uint32_t)((njp * 16 * AST + ks * 16) * 2));
                    unsigned bfa[2] = {tmp[0], tmp[1]};
                    unsigned bfb[2] = {tmp[2], tmp[3]};
                    mma_f16(sacc[2 * njp], qf[ks], bfa);
                    mma_f16(sacc[2 * njp + 1], qf[ks], bfb);
                }
            }

            // ---- scale (+mask only for diagonal-crossing tiles) + row max
            float mx0 = NEG_BIG, mx1 = NEG_BIG;
            if (kb + 63 > wrow) {        // mask path (<=2 tiles per warp)
#pragma unroll
                for (int nj = 0; nj < 8; nj++) {
                    int cg = kb + nj * 8 + 2 * tig;
                    float s0 = sacc[nj][0] * SCL;
                    float s1 = sacc[nj][1] * SCL;
                    float s2 = sacc[nj][2] * SCL;
                    float s3 = sacc[nj][3] * SCL;
                    if (cg > row0) s0 = NEG_BIG;
                    if (cg + 1 > row0) s1 = NEG_BIG;
                    if (cg > row1) s2 = NEG_BIG;
                    if (cg + 1 > row1) s3 = NEG_BIG;
                    sacc[nj][0] = s0; sacc[nj][1] = s1;
                    sacc[nj][2] = s2; sacc[nj][3] = s3;
                    mx0 = fmaxf(mx0, fmaxf(s0, s1));
                    mx1 = fmaxf(mx1, fmaxf(s2, s3));
                }
            } else {                     // fast path: no masking needed
#pragma unroll
                for (int nj = 0; nj < 8; nj++) {
                    float s0 = sacc[nj][0] * SCL;
                    float s1 = sacc[nj][1] * SCL;
                    float s2 = sacc[nj][2] * SCL;
                    float s3 = sacc[nj][3] * SCL;
                    sacc[nj][0] = s0; sacc[nj][1] = s1;
                    sacc[nj][2] = s2; sacc[nj][3] = s3;
                    mx0 = fmaxf(mx0, fmaxf(s0, s1));
                    mx1 = fmaxf(mx1, fmaxf(s2, s3));
                }
            }
            mx0 = fmaxf(mx0, __shfl_xor_sync(0xFFFFFFFFu, mx0, 1));
            mx0 = fmaxf(mx0, __shfl_xor_sync(0xFFFFFFFFu, mx0, 2));
            mx1 = fmaxf(mx1, __shfl_xor_sync(0xFFFFFFFFu, mx1, 1));
            mx1 = fmaxf(mx1, __shfl_xor_sync(0xFFFFFFFFu, mx1, 2));
            float mn0 = fmaxf(m0, mx0), mn1 = fmaxf(m1, mx1);

            // ---- exp2 + sums; P packed to fp16 A-fragments ----
            unsigned pe[8][2];
            float se0 = 0.f, se1 = 0.f, sw0 = 0.f, sw1 = 0.f;
#pragma unroll
            for (int nj = 0; nj < 8; nj++) {
                float s0 = sacc[nj][0], s1 = sacc[nj][1];
                float s2 = sacc[nj][2], s3 = sacc[nj][3];
                float e0 = exp2f(s0 - mn0), e1 = exp2f(s1 - mn0);
                float e2 = exp2f(s2 - mn1), e3 = exp2f(s3 - mn1);
                se0 += e0 + e1; sw0 += e0 * s0 + e1 * s1;
                se1 += e2 + e3; sw1 += e2 * s2 + e3 * s3;
                pe[nj][0] = pack_h2(e0, e1);
                pe[nj][1] = pack_h2(e2, e3);
            }
            se0 += __shfl_xor_sync(0xFFFFFFFFu, se0, 1);
            se0 += __shfl_xor_sync(0xFFFFFFFFu, se0, 2);
            sw0 += __shfl_xor_sync(0xFFFFFFFFu, sw0, 1);
            sw0 += __shfl_xor_sync(0xFFFFFFFFu, sw0, 2);
            se1 += __shfl_xor_sync(0xFFFFFFFFu, se1, 1);
            se1 += __shfl_xor_sync(0xFFFFFFFFu, se1, 2);
            sw1 += __shfl_xor_sync(0xFFFFFFFFu, sw1, 1);
            sw1 += __shfl_xor_sync(0xFFFFFFFFu, sw1, 2);

            float c0f = exp2f(m0 - mn0), c1f = exp2f(m1 - mn1);
            l0 = l0 * c0f + se0; w0 = w0 * c0f + sw0; m0 = mn0;
            l1 = l1 * c1f + se1; w1 = w1 * c1f + sw1; m1 = mn1;
#pragma unroll
            for (int nj = 0; nj < 8; nj++) {
                oacc[nj][0] *= c0f; oacc[nj][1] *= c0f;
                oacc[nj][2] *= c1f; oacc[nj][3] *= c1f;
            }

            // ---- O += P V ----
            uint32_t vbase = vs_u32 + (uint32_t)((i & 1) * KVN * 2) + v_lm;
#pragma unroll
            for (int ks = 0; ks < 4; ks++) {
                unsigned af[4] = { pe[2 * ks][0], pe[2 * ks][1],
                                   pe[2 * ks + 1][0], pe[2 * ks + 1][1] };
#pragma unroll
                for (int dj = 0; dj < 4; dj++) {
                    uint32_t addr = vbase + (uint32_t)((ks * 16 * AST + dj * 16) * 2);
                    unsigned v0, v1, v2, v3;
                    asm volatile(
                        "ldmatrix.sync.aligned.m8n8.x4.trans.shared.b16 "
                        "{%0,%1,%2,%3}, [%4];"
                        : "=r"(v0), "=r"(v1), "=r"(v2), "=r"(v3) : "r"(addr));
                    unsigned bfa[2] = {v0, v1};
                    unsigned bfb[2] = {v2, v3};
                    mma_f16(oacc[2 * dj], af, bfa);
                    mma_f16(oacc[2 * dj + 1], af, bfb);
                }
            }
        }
    }

    // write O (divide by l) as fp16
    {
        float li0 = 1.0f / l0, li1 = 1.0f / l1;
#pragma unroll
        for (int nj = 0; nj < 8; nj++) {
            int c = h * HD + nj * 8 + 2 * tig;
            *(__half2*)&y[(size_t)(b * TDIM + row0) * CDIM + c] =
                __floats2half2_rn(oacc[nj][0] * li0, oacc[nj][1] * li0);
            *(__half2*)&y[(size_t)(b * TDIM + row1) * CDIM + c] =
                __floats2half2_rn(oacc[nj][2] * li1, oacc[nj][3] * li1);
        }
    }

    // entropy: log2-domain state -> H = (m' - W'/l)*ln2 + ln(l)
    if (tig == 0) {
        hrow[warp * 16 + g]     = (m0 - w0 / l0) * RLOG2E + logf(l0);
        hrow[warp * 16 + g + 8] = (m1 - w1 / l1) * RLOG2E + logf(l1);
    }
    __syncthreads();
    if (tid == 0) {
        float tot = 0.f;
        for (int i = 0; i < 128; i++) tot += hrow[i];
        atomicAdd(&g_ent, tot);
    }
}

// ------------------------------------------------------------------
extern "C" void kernel_launch(void* const* d_in, const int* in_sizes, int n_in,
                              void* d_out, int out_size) {
    const float* x          = (const float*)d_in[0];
    const float* ln1_w      = (const float*)d_in[1];
    const float* ln1_b      = (const float*)d_in[2];
    const float* attn_w     = (const float*)d_in[3];
    const float* attn_b     = (const float*)d_in[4];
    const float* attnproj_w = (const float*)d_in[5];
    const float* attnproj_b = (const float*)d_in[6];
    const float* ln2_w      = (const float*)d_in[7];
    const float* ln2_b      = (const float*)d_in[8];
    const float* fc_w       = (const float*)d_in[9];
    const float* fc_b       = (const float*)d_in[10];
    const float* proj_w     = (const float*)d_in[11];
    const float* proj_b     = (const float*)d_in[12];
    float* out = (float*)d_out;

    __half *p_h, *p_qkv, *p_y, *p_m, *p_wh;
    float *p_x1;
    cudaGetSymbolAddress((void**)&p_h,   g_h);
    cudaGetSymbolAddress((void**)&p_qkv, g_qkv);
    cudaGetSymbolAddress((void**)&p_y,   g_y);
    cudaGetSymbolAddress((void**)&p_x1,  g_x1);
    cudaGetSymbolAddress((void**)&p_m,   g_m);
    cudaGetSymbolAddress((void**)&p_wh,  g_wh);

    static int gemm_smem = 6 * HBUF * 2;                          // 110592 B
    static int attn_smem = (128 * AST + 4 * KVN) * 2 + 128 * 4;   // ~56 KB
    cudaFuncSetAttribute(gemm_f16,
                         cudaFuncAttributeMaxDynamicSharedMemorySize, gemm_smem);
    cudaFuncSetAttribute(flash_attn_f16,
                         cudaFuncAttributeMaxDynamicSharedMemorySize, attn_smem);

    float* entOut = (out_size > BT * CDIM) ? out + BT * CDIM : nullptr;

    // RN-convert all weights to fp16 in one launch
    tohalf_all_kernel<<<WR_TOT / 1024, 256>>>(attn_w, attnproj_w, fc_w, proj_w, p_wh);

    // h = LN1(x)  (fp16 out; zeroes g_ent)
    ln_kernel<<<BT, 256>>>(x, ln1_w, ln1_b, p_h, 1);

    // qkv = h @ attn_w^T + attn_b   (fp16 out)
    gemm_f16<<<dim3(QKVC / 128, BT / 128), 256, gemm_smem>>>(
        p_h, p_wh + WR_ATTN, attn_b, nullptr, p_qkv, BT, QKVC, CDIM, 0, 1, nullptr);

    // attention (+entropy) -> y fp16
    flash_attn_f16<<<dim3(TDIM / 128, BH), 256, attn_smem>>>(p_qkv, p_y);

    // x1 = x + y @ attnproj_w^T + attnproj_b   (fp32 out)
    gemm_f16<<<dim3(CDIM / 128, BT / 128), 256, gemm_smem>>>(
        p_y, p_wh + WR_APROJ, attnproj_b, x, p_x1, BT, CDIM, CDIM, 0, 0, nullptr);

    // h = LN2(x1)  (fp16 out)
    ln_kernel<<<BT, 256>>>(p_x1, ln2_w, ln2_b, p_h, 0);

    // m = gelu(h @ fc_w^T + fc_b)   (fp16 out)
    gemm_f16<<<dim3(FFC / 128, BT / 128), 256, gemm_smem>>>(
        p_h, p_wh + WR_FC, fc_b, nullptr, p_m, BT, FFC, CDIM, 1, 1, nullptr);

    // out = x1 + m @ proj_w^T + proj_b   (fp32 out; writes entropy scalar)
    gemm_f16<<<dim3(CDIM / 128, BT / 128), 256, gemm_smem>>>(
        p_m, p_wh + WR_PROJ, proj_b, p_x1, out, BT, CDIM, FFC, 0, 0, entOut);
}